// round 7
// baseline (speedup 1.0000x reference)
#include <cuda_runtime.h>
#include <cuda_bf16.h>
#include <math.h>
#include <stdint.h>

#define NN    50000
#define EE    400000
#define HID   128
#define RBF_COEFF (-19.22f)

// ---------------- scratch ----------------
__device__ float g_v1[(size_t)NN * 3 * HID];
__device__ float g_v2[(size_t)NN * 3 * HID];
__device__ float g_v3[(size_t)NN * 3 * HID];
__device__ float g_vdot[(size_t)NN * HID];
__device__ float g_haggr[(size_t)NN * HID];
__device__ float g_vaggr[(size_t)NN * 3 * HID];
// weight image: panel-pairs [hi 16KB | lo 16KB], [n=128][k=64] bf16, SW128 swizzle
__device__ __align__(16) unsigned char g_wimg[491520];
#define IMG_B2 229376u
#define IMG_B3 294912u

// ---------------- helpers ----------------
__device__ __forceinline__ uint32_t smem_u32(const void* p) {
    uint32_t a;
    asm("{ .reg .u64 t; cvta.to.shared.u64 t, %1; cvt.u32.u64 %0, t; }" : "=r"(a) : "l"(p));
    return a;
}
__device__ __forceinline__ uint32_t amap(int m, int k) {
    return (((uint32_t)(m >> 3)) << 10) + (((uint32_t)(m & 7)) << 7)
         + ((((uint32_t)k << 1)) ^ (((uint32_t)(m & 7)) << 4));
}
__device__ __forceinline__ void hilo(float v, unsigned short& hi, unsigned short& lo) {
    __nv_bfloat16 h = __float2bfloat16(v);
    hi = __bfloat16_as_ushort(h);
    lo = __bfloat16_as_ushort(__float2bfloat16(v - __bfloat162float(h)));
}
__device__ __forceinline__ void ldsm4(uint32_t r[4], uint32_t addr) {
    asm volatile("ldmatrix.sync.aligned.m8n8.x4.shared.b16 {%0,%1,%2,%3}, [%4];"
        : "=r"(r[0]), "=r"(r[1]), "=r"(r[2]), "=r"(r[3]) : "r"(addr));
}
__device__ __forceinline__ void mma16816(float c[4], const uint32_t a[4], uint32_t b0, uint32_t b1) {
    asm volatile("mma.sync.aligned.m16n8k16.row.col.f32.bf16.bf16.f32 "
        "{%0,%1,%2,%3}, {%4,%5,%6,%7}, {%8,%9}, {%0,%1,%2,%3};"
        : "+f"(c[0]), "+f"(c[1]), "+f"(c[2]), "+f"(c[3])
        : "r"(a[0]), "r"(a[1]), "r"(a[2]), "r"(a[3]), "r"(b0), "r"(b1));
}
#define RED2(p, a, b) \
    asm volatile("red.global.add.v2.f32 [%0], {%1,%2};" :: "l"(p), "f"(a), "f"(b) : "memory")
#define CPA16(sa, gp) asm volatile("cp.async.cg.shared.global [%0], [%1], 16;" :: "r"(sa), "l"(gp))
#define CPA_COMMIT()  asm volatile("cp.async.commit_group;" ::: "memory")
#define CPA_WAIT0()   asm volatile("cp.async.wait_group 0;" ::: "memory")
#define CPA_WAIT1()   asm volatile("cp.async.wait_group 1;" ::: "memory")

// panel schedule: 15 weight panel-pairs
__device__ __forceinline__ uint32_t woff(int i) {
    if (i < 7)  return (uint32_t)i * 32768u;                       // L1
    if (i < 9)  return IMG_B2 + (uint32_t)(i - 7) * 32768u;        // L2
    if (i < 11) return IMG_B3 + (uint32_t)(i - 9 + 4) * 32768u;    // L3 t=2 (msg_x)
    if (i < 13) return IMG_B3 + (uint32_t)(i - 11 + 2) * 32768u;   // L3 t=1 (msg_v)
    return IMG_B3 + (uint32_t)(i - 13) * 32768u;                   // L3 t=0 (msg_h)
}

// ======================= weight prep (unchanged layout) =======================
__global__ void k_prep(const float* __restrict__ W1, const float* __restrict__ b1,
                       const float* __restrict__ W2, const float* __restrict__ W3) {
    int idx = blockIdx.x * 256 + threadIdx.x;
    if (idx >= 122880) return;
    float v; uint32_t off;
    if (idx < 57344) {                       // L1 K-order: h_row|h_col|cross|rbf|ea|bias|0
        int k = idx >> 7, n = idx & 127;
        if      (k < 256)  v = W1[(size_t)k * HID + n];
        else if (k < 384)  v = W1[(size_t)(k + 32) * HID + n];   // cross (W1 rows 288..415)
        else if (k < 416)  v = W1[(size_t)(k - 128) * HID + n];  // rbf   (W1 rows 256..287)
        else if (k < 432)  v = W1[(size_t)k * HID + n];          // eattr (W1 rows 416..431)
        else if (k == 432) v = b1[n];
        else               v = 0.f;
        off = (uint32_t)(k >> 6) * 32768u + amap(n, k & 63);
    } else if (idx < 73728) {                // L2
        int i2 = idx - 57344, k = i2 >> 7, n = i2 & 127;
        v = W2[(size_t)k * HID + n];
        off = IMG_B2 + (uint32_t)(k >> 6) * 32768u + amap(n, k & 63);
    } else {                                 // L3 tile t
        int i3 = idx - 73728, t = i3 >> 14, rem = i3 & 16383, k = rem >> 7, n = rem & 127;
        v = W3[(size_t)k * 384 + 128 * t + n];
        off = IMG_B3 + (uint32_t)(t * 2 + (k >> 6)) * 32768u + amap(n, k & 63);
    }
    unsigned short hi, lo; hilo(v, hi, lo);
    *(unsigned short*)(g_wimg + off)         = hi;
    *(unsigned short*)(g_wimg + off + 16384) = lo;
}

// ======================= zero =======================
__global__ void k_zero() {
    int i = blockIdx.x * blockDim.x + threadIdx.x;
    const int n1 = NN * HID / 4;
    float4 z = make_float4(0.f, 0.f, 0.f, 0.f);
    if (i < n1) reinterpret_cast<float4*>(g_haggr)[i] = z;
    else        reinterpret_cast<float4*>(g_vaggr)[i - n1] = z;
}

// ======================= node pre (fp32) =======================
__global__ __launch_bounds__(128) void k_node_pre(const float* __restrict__ vec,
                                                  const float* __restrict__ Wvp) {
    __shared__ __align__(16) float vsh[8][3][HID];
    const int n0 = blockIdx.x * 8, tid = threadIdx.x;
    for (int idx = tid; idx < 8 * 3 * HID; idx += 128)
        ((float*)vsh)[idx] = vec[(size_t)n0 * 3 * HID + idx];
    __syncthreads();
    const int u = tid & 31, g = tid >> 5;
    float a[2][3][3][4];
#pragma unroll
    for (int r = 0; r < 2; r++)
#pragma unroll
        for (int v = 0; v < 3; v++)
#pragma unroll
            for (int o = 0; o < 3; o++)
#pragma unroll
                for (int q = 0; q < 4; q++) a[r][v][o][q] = 0.f;
    for (int i = 0; i < HID; i++) {
        float4 w0 = *(const float4*)&Wvp[i * 384 + 4 * u];
        float4 w1 = *(const float4*)&Wvp[i * 384 + 128 + 4 * u];
        float4 w2 = *(const float4*)&Wvp[i * 384 + 256 + 4 * u];
        float wa[4] = {w0.x, w0.y, w0.z, w0.w};
        float wb[4] = {w1.x, w1.y, w1.z, w1.w};
        float wc[4] = {w2.x, w2.y, w2.z, w2.w};
#pragma unroll
        for (int r = 0; r < 2; r++)
#pragma unroll
            for (int v = 0; v < 3; v++) {
                float x = vsh[2 * g + r][v][i];
#pragma unroll
                for (int q = 0; q < 4; q++) {
                    a[r][v][0][q] += x * wa[q];
                    a[r][v][1][q] += x * wb[q];
                    a[r][v][2][q] += x * wc[q];
                }
            }
    }
#pragma unroll
    for (int r = 0; r < 2; r++) {
        int n = n0 + 2 * g + r;
        float vd[4] = {0.f, 0.f, 0.f, 0.f};
#pragma unroll
        for (int v = 0; v < 3; v++) {
            size_t base = ((size_t)n * 3 + v) * HID + 4 * u;
            *(float4*)&g_v1[base] = make_float4(a[r][v][0][0], a[r][v][0][1], a[r][v][0][2], a[r][v][0][3]);
            *(float4*)&g_v2[base] = make_float4(a[r][v][1][0], a[r][v][1][1], a[r][v][1][2], a[r][v][1][3]);
            *(float4*)&g_v3[base] = make_float4(a[r][v][2][0], a[r][v][2][1], a[r][v][2][2], a[r][v][2][3]);
#pragma unroll
            for (int q = 0; q < 4; q++) vd[q] += a[r][v][0][q] * a[r][v][1][q];
        }
        *(float4*)&g_vdot[(size_t)n * HID + 4 * u] = make_float4(vd[0], vd[1], vd[2], vd[3]);
    }
}

// ======================= tensorized edge kernel (64 edges/CTA, pipelined B) =======================
// SMEM: AC union 32KB: L1 A-build (hi@0, lo@8192) THEN activations (hi q*8192, lo 16384+q*8192)
//       B ping-pong 2x32KB @32768 ; meta @98304
#define SMM_AC 0u
#define SMM_B  32768u
#define SMM_META 98304u
#define SMM_TOT  102400

__global__ void __launch_bounds__(256, 2) k_edge_m(const float* __restrict__ h,
                                                   const float* __restrict__ coord,
                                                   const int*   __restrict__ ei,
                                                   const float* __restrict__ eattr,
                                                   const float* __restrict__ b2g,
                                                   const float* __restrict__ b3g) {
    extern __shared__ __align__(1024) unsigned char sm[];
    const int tid = threadIdx.x, w = tid >> 5, l = tid & 31;
    const int e0 = blockIdx.x * 64;
    const uint32_t sb = smem_u32(sm);
    int*   row_sh = (int*)  (sm + SMM_META);
    int*   col_sh = (int*)  (sm + SMM_META + 256);
    float* xij    = (float*)(sm + SMM_META + 512);
    float* dsh    = (float*)(sm + SMM_META + 1280);
    float* sb2    = (float*)(sm + SMM_META + 1536);
    float* sb3    = (float*)(sm + SMM_META + 2048);

#define COPYB(goff, s) do { \
    const unsigned char* _s = g_wimg + (goff); \
    uint32_t _d = sb + SMM_B + (uint32_t)(s) * 32768u; \
    for (int _i = tid; _i < 2048; _i += 256) \
        CPA16(_d + ((uint32_t)_i << 4), _s + ((size_t)_i << 4)); \
    CPA_COMMIT(); } while (0)

    // start first weight copy immediately
    COPYB(woff(0), 0);

    if (tid < 128) sb2[tid] = b2g[tid];
    if (tid < 192) { sb3[tid * 2] = b3g[tid * 2]; sb3[tid * 2 + 1] = b3g[tid * 2 + 1]; }
    if (tid < 64) {
        int e = e0 + tid;
        int r = ei[e], c = ei[EE + e];
        row_sh[tid] = r; col_sh[tid] = c;
        float dx = coord[3 * r] - coord[3 * c];
        float dy = coord[3 * r + 1] - coord[3 * c + 1];
        float dz = coord[3 * r + 2] - coord[3 * c + 2];
        xij[3 * tid] = dx; xij[3 * tid + 1] = dy; xij[3 * tid + 2] = dz;
        dsh[tid] = sqrtf(dx * dx + dy * dy + dz * dz + 1e-8f);
    }
    __syncthreads();

    // --- per-lane fragment addressing ---
    const int wm = w & 3, nh = w >> 2;
    const int gr = (wm << 4) + (l >> 2);
    const uint32_t a_lane = (((uint32_t)(2 * wm + ((l >> 3) & 1))) << 10) | (((uint32_t)(l & 7)) << 7);
    const uint32_t lmask  = ((uint32_t)(l & 7)) << 4;
    const int ak_extra = (l >> 4) << 3;
    const uint32_t b_lane = (((uint32_t)((l >> 4) & 1)) << 10) | (((uint32_t)(l & 7)) << 7);
    const uint32_t nh_off = (uint32_t)nh * 8192u;
    const int bk_extra = (l & 8);
    const int cq = 2 * (l & 3);

    float acc[8][4];
#pragma unroll
    for (int t = 0; t < 8; t++)
#pragma unroll
        for (int q = 0; q < 4; q++) acc[t][q] = 0.f;

#define RUN4(ACC, APAN, ALOFF, BUF) do { \
    uint32_t _bb = sb + SMM_B + (uint32_t)(BUF) * 32768u; \
    _Pragma("unroll") \
    for (int s = 0; s < 4; s++) { \
        int kb = s << 4; \
        uint32_t aHi = sb + (APAN) + a_lane + ((((uint32_t)(kb + ak_extra)) << 1) ^ lmask); \
        uint32_t bHi = _bb + b_lane + nh_off + ((((uint32_t)(kb + bk_extra)) << 1) ^ lmask); \
        uint32_t ah[4], al[4]; \
        ldsm4(ah, aHi); ldsm4(al, aHi + (ALOFF)); \
        _Pragma("unroll") \
        for (int np = 0; np < 4; np++) { \
            uint32_t bh[4], bl[4]; \
            ldsm4(bh, bHi + ((uint32_t)np << 11)); \
            ldsm4(bl, bHi + 16384u + ((uint32_t)np << 11)); \
            mma16816((ACC)[2 * np],     ah, bh[0], bh[1]); \
            mma16816((ACC)[2 * np],     al, bh[0], bh[1]); \
            mma16816((ACC)[2 * np],     ah, bl[0], bl[1]); \
            mma16816((ACC)[2 * np + 1], ah, bh[2], bh[3]); \
            mma16816((ACC)[2 * np + 1], al, bh[2], bh[3]); \
            mma16816((ACC)[2 * np + 1], ah, bl[2], bl[3]); \
        } \
    } } while (0)

// generic pipelined GEMM step for panels i>=7 (no A build)
#define STEP(ACC, APAN, I) do { \
    if ((I) < 14) { COPYB(woff((I) + 1), ((I) + 1) & 1); CPA_WAIT1(); } else CPA_WAIT0(); \
    __syncthreads(); \
    RUN4(ACC, APAN, 16384u, (I) & 1); \
    __syncthreads(); } while (0)

    // ---------------- Layer 1: panels 0..6, A built per panel ----------------
    {
        const int ee = tid & 63, quarter = tid >> 6;
        const int rr = row_sh[ee], cc = col_sh[ee];
        const int rot = (ee >> 3) & 3;
        for (int p = 0; p < 7; p++) {
            COPYB(woff(p + 1), (p + 1) & 1);      // prefetch next weights
            // build A panel p (64 rows x 64 cols, hi/lo) — overlaps the copy
#pragma unroll
            for (int jj = 0; jj < 2; jj++) {
                int j = ((quarter * 2 + jj) + rot * 2) & 7;
                int kl = 8 * j;
                float v[8];
                if (p < 4) {
                    int node = (p < 2) ? rr : cc;
                    int base = 64 * (p & 1) + kl;
                    float4 a4 = *(const float4*)&h[(size_t)node * HID + base];
                    float4 b4 = *(const float4*)&h[(size_t)node * HID + base + 4];
                    v[0]=a4.x; v[1]=a4.y; v[2]=a4.z; v[3]=a4.w;
                    v[4]=b4.x; v[5]=b4.y; v[6]=b4.z; v[7]=b4.w;
                } else if (p < 6) {
                    int base = 64 * (p - 4) + kl;
#pragma unroll
                    for (int q = 0; q < 8; q++) v[q] = 0.f;
#pragma unroll
                    for (int vv = 0; vv < 3; vv++) {
                        const float* p1 = &g_v1[((size_t)rr * 3 + vv) * HID + base];
                        const float* p2 = &g_v2[((size_t)cc * 3 + vv) * HID + base];
                        float4 a4 = *(const float4*)p1, a5 = *(const float4*)(p1 + 4);
                        float4 c4 = *(const float4*)p2, c5 = *(const float4*)(p2 + 4);
                        v[0]+=a4.x*c4.x; v[1]+=a4.y*c4.y; v[2]+=a4.z*c4.z; v[3]+=a4.w*c4.w;
                        v[4]+=a5.x*c5.x; v[5]+=a5.y*c5.y; v[6]+=a5.z*c5.z; v[7]+=a5.w*c5.w;
                    }
                } else {
                    float dd = dsh[ee];
#pragma unroll
                    for (int q = 0; q < 8; q++) {
                        int kk = kl + q;
                        if (kk < 32) { float t0 = dd - (5.f / 31.f) * kk; v[q] = __expf(RBF_COEFF * t0 * t0); }
                        else if (kk < 48) v[q] = eattr[(size_t)(e0 + ee) * 16 + (kk - 32)];
                        else v[q] = (kk == 48) ? 1.f : 0.f;
                    }
                }
                uint32_t hh[4], ll[4];
#pragma unroll
                for (int m = 0; m < 4; m++) {
                    unsigned short h1, l1, h2, l2;
                    hilo(v[2 * m], h1, l1); hilo(v[2 * m + 1], h2, l2);
                    hh[m] = (uint32_t)h1 | ((uint32_t)h2 << 16);
                    ll[m] = (uint32_t)l1 | ((uint32_t)l2 << 16);
                }
                uint32_t off = amap(ee, kl);
                *(uint4*)(sm + SMM_AC + off)         = make_uint4(hh[0], hh[1], hh[2], hh[3]);
                *(uint4*)(sm + SMM_AC + 8192u + off) = make_uint4(ll[0], ll[1], ll[2], ll[3]);
            }
            CPA_WAIT1();           // panel p's weights arrived (p+1 still in flight)
            __syncthreads();
            RUN4(acc, SMM_AC, 8192u, p & 1);
            __syncthreads();
        }
    }
    // epilogue 1: silu (bias folded), store hi/lo activations into AC union
#pragma unroll
    for (int nt = 0; nt < 8; nt++) {
        int col = 64 * nh + 8 * nt + cq;
        uint32_t pan = (col >= 64) ? 8192u : 0u;
        uint32_t ko = (uint32_t)(col & 63);
#pragma unroll
        for (int hf = 0; hf < 2; hf++) {
            int row = gr + 8 * hf;
            float z0 = acc[nt][2 * hf], z1 = acc[nt][2 * hf + 1];
            z0 = z0 / (1.f + __expf(-z0));
            z1 = z1 / (1.f + __expf(-z1));
            unsigned short h0, l0, h1, l1;
            hilo(z0, h0, l0); hilo(z1, h1, l1);
            uint32_t off = pan + amap(row, ko);
            *(uint32_t*)(sm + SMM_AC + off)          = (uint32_t)h0 | ((uint32_t)h1 << 16);
            *(uint32_t*)(sm + SMM_AC + 16384u + off) = (uint32_t)l0 | ((uint32_t)l1 << 16);
        }
    }
    __syncthreads();

    // ---------------- Layer 2: panels 7,8 ----------------
#pragma unroll
    for (int t = 0; t < 8; t++)
#pragma unroll
        for (int q = 0; q < 4; q++) acc[t][q] = 0.f;
    STEP(acc, SMM_AC + 0u,    7);
    STEP(acc, SMM_AC + 8192u, 8);
    // epilogue 2: +b2, silu, overwrite AC with A3
#pragma unroll
    for (int nt = 0; nt < 8; nt++) {
        int col = 64 * nh + 8 * nt + cq;
        uint32_t pan = (col >= 64) ? 8192u : 0u;
        uint32_t ko = (uint32_t)(col & 63);
        float bb0 = sb2[col], bb1 = sb2[col + 1];
#pragma unroll
        for (int hf = 0; hf < 2; hf++) {
            int row = gr + 8 * hf;
            float z0 = acc[nt][2 * hf] + bb0, z1 = acc[nt][2 * hf + 1] + bb1;
            z0 = z0 / (1.f + __expf(-z0));
            z1 = z1 / (1.f + __expf(-z1));
            unsigned short h0, l0, h1, l1;
            hilo(z0, h0, l0); hilo(z1, h1, l1);
            uint32_t off = pan + amap(row, ko);
            *(uint32_t*)(sm + SMM_AC + off)          = (uint32_t)h0 | ((uint32_t)h1 << 16);
            *(uint32_t*)(sm + SMM_AC + 16384u + off) = (uint32_t)l0 | ((uint32_t)l1 << 16);
        }
    }
    __syncthreads();

    // ---------------- Layer 3 ----------------
    {
        float acx[8][4];
        // t=2 (msg_x): panels 9,10
#pragma unroll
        for (int t = 0; t < 8; t++)
#pragma unroll
            for (int q = 0; q < 4; q++) acx[t][q] = 0.f;
        STEP(acx, SMM_AC + 0u,    9);
        STEP(acx, SMM_AC + 8192u, 10);
        // t=1 (msg_v): panels 11,12
#pragma unroll
        for (int t = 0; t < 8; t++)
#pragma unroll
            for (int q = 0; q < 4; q++) acc[t][q] = 0.f;
        STEP(acc, SMM_AC + 0u,    11);
        STEP(acc, SMM_AC + 8192u, 12);
        // biases
#pragma unroll
        for (int nt = 0; nt < 8; nt++) {
            int col = 64 * nh + 8 * nt + cq;
#pragma unroll
            for (int hf = 0; hf < 2; hf++) {
                acx[nt][2 * hf]     += sb3[256 + col];
                acx[nt][2 * hf + 1] += sb3[256 + col + 1];
                acc[nt][2 * hf]     += sb3[128 + col];
                acc[nt][2 * hf + 1] += sb3[128 + col + 1];
            }
        }
        // scatter vaggr (overlaps panels 13,14 copies)
#pragma unroll 1
        for (int hf = 0; hf < 2; hf++) {
            int er = gr + 8 * hf;
            int ro = row_sh[er], co = col_sh[er];
            float x0 = xij[3 * er], x1 = xij[3 * er + 1], x2 = xij[3 * er + 2];
#pragma unroll 1
            for (int v = 0; v < 3; v++) {
                float xv = (v == 0) ? x0 : (v == 1) ? x1 : x2;
                const float* vbp = &g_v3[((size_t)co * 3 + v) * HID];
                float* abp = &g_vaggr[((size_t)ro * 3 + v) * HID];
#pragma unroll
                for (int nt = 0; nt < 8; nt++) {
                    int c0 = 64 * nh + 8 * nt + cq;
                    float2 v3v = *(const float2*)(vbp + c0);
                    RED2(abp + c0,
                         v3v.x * acc[nt][2 * hf]     + acx[nt][2 * hf]     * xv,
                         v3v.y * acc[nt][2 * hf + 1] + acx[nt][2 * hf + 1] * xv);
                }
            }
        }
        // t=0 (msg_h): panels 13,14 -> acx (reuse), scatter haggr
#pragma unroll
        for (int t = 0; t < 8; t++)
#pragma unroll
            for (int q = 0; q < 4; q++) acx[t][q] = 0.f;
        STEP(acx, SMM_AC + 0u,    13);
        STEP(acx, SMM_AC + 8192u, 14);
#pragma unroll 1
        for (int hf = 0; hf < 2; hf++) {
            int er = gr + 8 * hf;
            int ro = row_sh[er];
            float* hbp = &g_haggr[(size_t)ro * HID];
#pragma unroll
            for (int nt = 0; nt < 8; nt++) {
                int c0 = 64 * nh + 8 * nt + cq;
                RED2(hbp + c0,
                     acx[nt][2 * hf]     + sb3[c0],
                     acx[nt][2 * hf + 1] + sb3[c0 + 1]);
            }
        }
    }
#undef RUN4
#undef STEP
#undef COPYB
}

// ======================= node out (fp32) =======================
__global__ __launch_bounds__(128) void k_node_out(const float* __restrict__ Wop,
                                                  const float* __restrict__ bop,
                                                  float* __restrict__ out) {
    __shared__ __align__(16) float hsh[16][HID];
    const int n0 = blockIdx.x * 16, tid = threadIdx.x;
    for (int idx = tid; idx < 16 * HID; idx += 128)
        ((float*)hsh)[idx] = g_haggr[(size_t)n0 * HID + idx];
    __syncthreads();
    const int u = tid & 31, g = tid >> 5;
    float o1[4][4], o2[4][4], o3[4][4];
#pragma unroll
    for (int r = 0; r < 4; r++)
#pragma unroll
        for (int q = 0; q < 4; q++) { o1[r][q] = 0.f; o2[r][q] = 0.f; o3[r][q] = 0.f; }
    for (int i = 0; i < HID; i++) {
        float4 a4 = *(const float4*)&Wop[(size_t)i * 384 + 4 * u];
        float4 b4 = *(const float4*)&Wop[(size_t)i * 384 + 128 + 4 * u];
        float4 c4 = *(const float4*)&Wop[(size_t)i * 384 + 256 + 4 * u];
        float wa[4] = {a4.x, a4.y, a4.z, a4.w};
        float wb[4] = {b4.x, b4.y, b4.z, b4.w};
        float wc[4] = {c4.x, c4.y, c4.z, c4.w};
#pragma unroll
        for (int r = 0; r < 4; r++) {
            float x = hsh[4 * g + r][i];
#pragma unroll
            for (int q = 0; q < 4; q++) {
                o1[r][q] += x * wa[q];
                o2[r][q] += x * wb[q];
                o3[r][q] += x * wc[q];
            }
        }
    }
    float4 ba4 = *(const float4*)&bop[4 * u];
    float4 bb4 = *(const float4*)&bop[128 + 4 * u];
    float4 bc4 = *(const float4*)&bop[256 + 4 * u];
    float ba[4] = {ba4.x, ba4.y, ba4.z, ba4.w};
    float bb[4] = {bb4.x, bb4.y, bb4.z, bb4.w};
    float bc[4] = {bc4.x, bc4.y, bc4.z, bc4.w};
#pragma unroll 1
    for (int r = 0; r < 4; r++) {
        int n = n0 + 4 * g + r;
        float4 vd4 = *(const float4*)&g_vdot[(size_t)n * HID + 4 * u];
        float vd[4] = {vd4.x, vd4.y, vd4.z, vd4.w};
        float dh[4], O1[4];
#pragma unroll
        for (int q = 0; q < 4; q++) {
            O1[q] = o1[r][q] + ba[q];
            float O2 = o2[r][q] + bb[q];
            float O3 = o3[r][q] + bc[q];
            dh[q] = vd[q] * O2 + O3;
        }
        *(float4*)&out[(size_t)n * HID + 4 * u] = make_float4(dh[0], dh[1], dh[2], dh[3]);
#pragma unroll
        for (int v = 0; v < 3; v++) {
            size_t base = ((size_t)n * 3 + v) * HID + 4 * u;
            float4 v34 = *(const float4*)&g_v3[base];
            float4 va4 = *(const float4*)&g_vaggr[base];
            float dv[4] = {v34.x * O1[0] + va4.x, v34.y * O1[1] + va4.y,
                           v34.z * O1[2] + va4.z, v34.w * O1[3] + va4.w};
            *(float4*)&out[(size_t)NN * HID + base] = make_float4(dv[0], dv[1], dv[2], dv[3]);
        }
    }
}

// ======================= launch =======================
extern "C" void kernel_launch(void* const* d_in, const int* in_sizes, int n_in,
                              void* d_out, int out_size) {
    const float* h     = (const float*)d_in[0];
    const float* vec   = (const float*)d_in[1];
    const float* coord = (const float*)d_in[2];
    const int*   ei    = (const int*)  d_in[3];
    const float* eattr = (const float*)d_in[4];
    const float* Wvp   = (const float*)d_in[5];
    const float* W1    = (const float*)d_in[6];
    const float* b1    = (const float*)d_in[7];
    const float* W2    = (const float*)d_in[8];
    const float* b2    = (const float*)d_in[9];
    const float* W3    = (const float*)d_in[10];
    const float* b3    = (const float*)d_in[11];
    const float* Wop   = (const float*)d_in[12];
    const float* bop   = (const float*)d_in[13];
    float* out = (float*)d_out;

    cudaFuncSetAttribute(k_edge_m, cudaFuncAttributeMaxDynamicSharedMemorySize, SMM_TOT);
    k_prep<<<480, 256>>>(W1, b1, W2, W3);
    k_zero<<<25000, 256>>>();
    k_node_pre<<<NN / 8, 128>>>(vec, Wvp);
    k_edge_m<<<EE / 64, 256, SMM_TOT>>>(h, coord, ei, eattr, b2, b3);
    k_node_out<<<NN / 16, 128>>>(Wop, bop, out);
}

// round 11
// speedup vs baseline: 1.4427x; 1.4427x over previous
#include <cuda_runtime.h>
#include <cuda_bf16.h>
#include <math.h>
#include <stdint.h>

#define NN    50000
#define EE    400000
#define HID   128
#define RBF_COEFF (-19.22f)

// ---------------- scratch ----------------
__device__ float g_v1[(size_t)NN * 3 * HID];
__device__ float g_v2[(size_t)NN * 3 * HID];
__device__ float g_v3[(size_t)NN * 3 * HID];
__device__ float g_haggr[(size_t)NN * HID];
__device__ float g_vaggr[(size_t)NN * 3 * HID];
__device__ float g_o[(size_t)NN * 384];
// weight image: panel-pairs [hi 16KB | lo 16KB], [n=128][k=64] bf16, SW128 swizzle
__device__ __align__(16) unsigned char g_wimg[884736];
#define IMG_B2  229376u
#define IMG_B3  294912u
#define IMG_BVP 491520u
#define IMG_BOP 688128u

// ---------------- helpers ----------------
__device__ __forceinline__ uint32_t smem_u32(const void* p) {
    uint32_t a;
    asm("{ .reg .u64 t; cvta.to.shared.u64 t, %1; cvt.u32.u64 %0, t; }" : "=r"(a) : "l"(p));
    return a;
}
__device__ __forceinline__ uint32_t amap(int m, int k) {
    return (((uint32_t)(m >> 3)) << 10) + (((uint32_t)(m & 7)) << 7)
         + ((((uint32_t)k << 1)) ^ (((uint32_t)(m & 7)) << 4));
}
__device__ __forceinline__ void hilo(float v, unsigned short& hi, unsigned short& lo) {
    __nv_bfloat16 h = __float2bfloat16(v);
    hi = __bfloat16_as_ushort(h);
    lo = __bfloat16_as_ushort(__float2bfloat16(v - __bfloat162float(h)));
}
__device__ __forceinline__ void ldsm4(uint32_t r[4], uint32_t addr) {
    asm volatile("ldmatrix.sync.aligned.m8n8.x4.shared.b16 {%0,%1,%2,%3}, [%4];"
        : "=r"(r[0]), "=r"(r[1]), "=r"(r[2]), "=r"(r[3]) : "r"(addr));
}
__device__ __forceinline__ void mma16816(float c[4], const uint32_t a[4], uint32_t b0, uint32_t b1) {
    asm volatile("mma.sync.aligned.m16n8k16.row.col.f32.bf16.bf16.f32 "
        "{%0,%1,%2,%3}, {%4,%5,%6,%7}, {%8,%9}, {%0,%1,%2,%3};"
        : "+f"(c[0]), "+f"(c[1]), "+f"(c[2]), "+f"(c[3])
        : "r"(a[0]), "r"(a[1]), "r"(a[2]), "r"(a[3]), "r"(b0), "r"(b1));
}
#define RED2(p, a, b) \
    asm volatile("red.global.add.v2.f32 [%0], {%1,%2};" :: "l"(p), "f"(a), "f"(b) : "memory")
#define CPA16(sa, gp) asm volatile("cp.async.cg.shared.global [%0], [%1], 16;" :: "r"(sa), "l"(gp))
#define CPA_COMMIT()  asm volatile("cp.async.commit_group;" ::: "memory")
#define CPA_WAIT0()   asm volatile("cp.async.wait_group 0;" ::: "memory")
#define CPA_WAIT1()   asm volatile("cp.async.wait_group 1;" ::: "memory")

// ======================= weight prep =======================
__global__ void k_prep(const float* __restrict__ W1, const float* __restrict__ b1,
                       const float* __restrict__ W2, const float* __restrict__ W3,
                       const float* __restrict__ Wvp, const float* __restrict__ Wop) {
    int idx = blockIdx.x * 256 + threadIdx.x;
    if (idx >= 221184) return;
    float v; uint32_t off;
    if (idx < 57344) {                       // L1 K-order: h_row|h_col|cross|rbf|ea|bias|0
        int k = idx >> 7, n = idx & 127;
        if      (k < 256)  v = W1[(size_t)k * HID + n];
        else if (k < 384)  v = W1[(size_t)(k + 32) * HID + n];
        else if (k < 416)  v = W1[(size_t)(k - 128) * HID + n];
        else if (k < 432)  v = W1[(size_t)k * HID + n];
        else if (k == 432) v = b1[n];
        else               v = 0.f;
        off = (uint32_t)(k >> 6) * 32768u + amap(n, k & 63);
    } else if (idx < 73728) {                // L2
        int i2 = idx - 57344, k = i2 >> 7, n = i2 & 127;
        v = W2[(size_t)k * HID + n];
        off = IMG_B2 + (uint32_t)(k >> 6) * 32768u + amap(n, k & 63);
    } else if (idx < 122880) {               // L3 tile t
        int i3 = idx - 73728, t = i3 >> 14, rem = i3 & 16383, k = rem >> 7, n = rem & 127;
        v = W3[(size_t)k * 384 + 128 * t + n];
        off = IMG_B3 + (uint32_t)(t * 2 + (k >> 6)) * 32768u + amap(n, k & 63);
    } else if (idx < 172032) {               // Wvp tile t
        int i4 = idx - 122880, t = i4 >> 14, rem = i4 & 16383, k = rem >> 7, n = rem & 127;
        v = Wvp[(size_t)k * 384 + 128 * t + n];
        off = IMG_BVP + (uint32_t)(t * 2 + (k >> 6)) * 32768u + amap(n, k & 63);
    } else {                                 // Wop tile t
        int i5 = idx - 172032, t = i5 >> 14, rem = i5 & 16383, k = rem >> 7, n = rem & 127;
        v = Wop[(size_t)k * 384 + 128 * t + n];
        off = IMG_BOP + (uint32_t)(t * 2 + (k >> 6)) * 32768u + amap(n, k & 63);
    }
    unsigned short hi, lo; hilo(v, hi, lo);
    *(unsigned short*)(g_wimg + off)         = hi;
    *(unsigned short*)(g_wimg + off + 16384) = lo;
}

// ======================= zero =======================
__global__ void k_zero() {
    int i = blockIdx.x * blockDim.x + threadIdx.x;
    const int n1 = NN * HID / 4;
    float4 z = make_float4(0.f, 0.f, 0.f, 0.f);
    if (i < n1) reinterpret_cast<float4*>(g_haggr)[i] = z;
    else        reinterpret_cast<float4*>(g_vaggr)[i - n1] = z;
}

// ======================= generic 64-row GEMM: src[M,128] @ W[128,384] =======================
// mode 0: src=param (vec), dst v1/v2/v3 stride 128 ; mode 1: src=g_haggr, dst g_o stride 384
#define GM_A 0u          // hi q*8192 ; lo 16384 + q*8192
#define GM_B 32768u      // 2 x 32KB ping-pong
#define GM_TOT 98304

__global__ void __launch_bounds__(256, 2) k_gemm(const float* __restrict__ srcp,
                                                 int Mtot, uint32_t wbase, int mode) {
    extern __shared__ __align__(1024) unsigned char sm[];
    const int tid = threadIdx.x, w = tid >> 5, l = tid & 31;
    const int r0 = blockIdx.x * 64;
    const uint32_t sb = smem_u32(sm);
    const float* src = (mode == 0) ? srcp : g_haggr;

#define GCOPYB(goff, s) do { \
    const unsigned char* _s = g_wimg + (goff); \
    uint32_t _d = sb + GM_B + (uint32_t)(s) * 32768u; \
    for (int _i = tid; _i < 2048; _i += 256) \
        CPA16(_d + ((uint32_t)_i << 4), _s + ((size_t)_i << 4)); \
    CPA_COMMIT(); } while (0)

    GCOPYB(wbase, 0);

    // build A: 64 rows x 128 K, hi/lo, SW128 panels
    {
        const int ee = tid & 63, quarter = tid >> 6;
        int rg = r0 + ee;
        bool valid = rg < Mtot;
        const float* arow = src + (size_t)rg * 128;
        const int rot = (ee >> 3) & 3;
#pragma unroll
        for (int qp = 0; qp < 2; qp++) {
#pragma unroll
            for (int jj = 0; jj < 2; jj++) {
                int j = ((quarter * 2 + jj) + rot * 2) & 7;
                int kl = 8 * j;
                float v[8];
                if (valid) {
                    float4 a4 = *(const float4*)&arow[qp * 64 + kl];
                    float4 b4 = *(const float4*)&arow[qp * 64 + kl + 4];
                    v[0]=a4.x; v[1]=a4.y; v[2]=a4.z; v[3]=a4.w;
                    v[4]=b4.x; v[5]=b4.y; v[6]=b4.z; v[7]=b4.w;
                } else {
#pragma unroll
                    for (int q = 0; q < 8; q++) v[q] = 0.f;
                }
                uint32_t hh[4], ll[4];
#pragma unroll
                for (int m = 0; m < 4; m++) {
                    unsigned short h1, l1, h2, l2;
                    hilo(v[2 * m], h1, l1); hilo(v[2 * m + 1], h2, l2);
                    hh[m] = (uint32_t)h1 | ((uint32_t)h2 << 16);
                    ll[m] = (uint32_t)l1 | ((uint32_t)l2 << 16);
                }
                uint32_t off = (uint32_t)qp * 8192u + amap(ee, kl);
                *(uint4*)(sm + GM_A + off)          = make_uint4(hh[0], hh[1], hh[2], hh[3]);
                *(uint4*)(sm + GM_A + 16384u + off) = make_uint4(ll[0], ll[1], ll[2], ll[3]);
            }
        }
    }

    const int wm = w & 3, nh = w >> 2;
    const int gr = (wm << 4) + (l >> 2);
    const uint32_t a_lane = (((uint32_t)(2 * wm + ((l >> 3) & 1))) << 10) | (((uint32_t)(l & 7)) << 7);
    const uint32_t lmask  = ((uint32_t)(l & 7)) << 4;
    const int ak_extra = (l >> 4) << 3;
    const uint32_t b_lane = (((uint32_t)((l >> 4) & 1)) << 10) | (((uint32_t)(l & 7)) << 7);
    const uint32_t nh_off = (uint32_t)nh * 8192u;
    const int bk_extra = (l & 8);
    const int cq = 2 * (l & 3);

#define GRUN4(ACC, APAN, BUF) do { \
    uint32_t _bb = sb + GM_B + (uint32_t)(BUF) * 32768u; \
    _Pragma("unroll") \
    for (int s = 0; s < 4; s++) { \
        int kb = s << 4; \
        uint32_t aHi = sb + (APAN) + a_lane + ((((uint32_t)(kb + ak_extra)) << 1) ^ lmask); \
        uint32_t bHi = _bb + b_lane + nh_off + ((((uint32_t)(kb + bk_extra)) << 1) ^ lmask); \
        uint32_t ah[4], al[4]; \
        ldsm4(ah, aHi); ldsm4(al, aHi + 16384u); \
        _Pragma("unroll") \
        for (int np = 0; np < 4; np++) { \
            uint32_t bh[4], bl[4]; \
            ldsm4(bh, bHi + ((uint32_t)np << 11)); \
            ldsm4(bl, bHi + 16384u + ((uint32_t)np << 11)); \
            mma16816((ACC)[2 * np],     ah, bh[0], bh[1]); \
            mma16816((ACC)[2 * np],     al, bh[0], bh[1]); \
            mma16816((ACC)[2 * np],     ah, bl[0], bl[1]); \
            mma16816((ACC)[2 * np + 1], ah, bh[2], bh[3]); \
            mma16816((ACC)[2 * np + 1], al, bh[2], bh[3]); \
            mma16816((ACC)[2 * np + 1], ah, bl[2], bl[3]); \
        } \
    } } while (0)

    float acc[8][4];
    for (int t = 0; t < 3; t++) {
#pragma unroll
        for (int nt = 0; nt < 8; nt++)
#pragma unroll
            for (int q = 0; q < 4; q++) acc[nt][q] = 0.f;
        for (int q = 0; q < 2; q++) {
            int i = t * 2 + q;
            if (i < 5) { GCOPYB(wbase + (uint32_t)(i + 1) * 32768u, (i + 1) & 1); CPA_WAIT1(); }
            else CPA_WAIT0();
            __syncthreads();
            GRUN4(acc, GM_A + (uint32_t)q * 8192u, i & 1);
            __syncthreads();
        }
        // epilogue tile t
#pragma unroll
        for (int nt = 0; nt < 8; nt++) {
            int col = 64 * nh + 8 * nt + cq;
#pragma unroll
            for (int hf = 0; hf < 2; hf++) {
                int rg = r0 + gr + 8 * hf;
                if (rg < Mtot) {
                    float* p;
                    if (mode == 0) p = ((t == 0) ? g_v1 : (t == 1) ? g_v2 : g_v3) + (size_t)rg * 128 + col;
                    else           p = g_o + (size_t)rg * 384 + 128 * t + col;
                    *(float2*)p = make_float2(acc[nt][2 * hf], acc[nt][2 * hf + 1]);
                }
            }
        }
    }
#undef GRUN4
#undef GCOPYB
}

// ======================= final elementwise: dh, dvec (+vdot) =======================
__global__ __launch_bounds__(256) void k_final(const float* __restrict__ bop,
                                               float* __restrict__ out) {
    int g = blockIdx.x * 256 + threadIdx.x;           // 50000*32
    int n = g >> 5, c = (g & 31) * 4;
    const float* op = g_o + (size_t)n * 384;
    float4 o1 = *(const float4*)&op[c];
    float4 o2 = *(const float4*)&op[128 + c];
    float4 o3 = *(const float4*)&op[256 + c];
    float4 b1v = *(const float4*)&bop[c];
    float4 b2v = *(const float4*)&bop[128 + c];
    float4 b3v = *(const float4*)&bop[256 + c];
    o1.x += b1v.x; o1.y += b1v.y; o1.z += b1v.z; o1.w += b1v.w;
    o2.x += b2v.x; o2.y += b2v.y; o2.z += b2v.z; o2.w += b2v.w;
    o3.x += b3v.x; o3.y += b3v.y; o3.z += b3v.z; o3.w += b3v.w;
    float vd[4] = {0.f, 0.f, 0.f, 0.f};
#pragma unroll
    for (int v = 0; v < 3; v++) {
        size_t base = ((size_t)n * 3 + v) * 128 + c;
        float4 a = *(const float4*)&g_v1[base];
        float4 b = *(const float4*)&g_v2[base];
        vd[0] += a.x * b.x; vd[1] += a.y * b.y; vd[2] += a.z * b.z; vd[3] += a.w * b.w;
    }
    *(float4*)&out[(size_t)n * 128 + c] =
        make_float4(vd[0] * o2.x + o3.x, vd[1] * o2.y + o3.y,
                    vd[2] * o2.z + o3.z, vd[3] * o2.w + o3.w);
#pragma unroll
    for (int v = 0; v < 3; v++) {
        size_t base = ((size_t)n * 3 + v) * 128 + c;
        float4 v3 = *(const float4*)&g_v3[base];
        float4 va = *(const float4*)&g_vaggr[base];
        *(float4*)&out[(size_t)NN * 128 + base] =
            make_float4(v3.x * o1.x + va.x, v3.y * o1.y + va.y,
                        v3.z * o1.z + va.z, v3.w * o1.w + va.w);
    }
}

// ======================= tensorized edge kernel (R6 version, 64 edges/CTA, 2 CTA/SM) =======================
#define SMM_A 0u
#define SMM_C 16384u
#define SMM_B 49152u
#define SMM_META 81920u
#define SMM_TOT  86016

__global__ void __launch_bounds__(256, 2) k_edge_m(const float* __restrict__ h,
                                                   const float* __restrict__ coord,
                                                   const int*   __restrict__ ei,
                                                   const float* __restrict__ eattr,
                                                   const float* __restrict__ b2g,
                                                   const float* __restrict__ b3g) {
    extern __shared__ __align__(1024) unsigned char sm[];
    const int tid = threadIdx.x, w = tid >> 5, l = tid & 31;
    const int e0 = blockIdx.x * 64;
    const uint32_t sb = smem_u32(sm);
    int*   row_sh = (int*)  (sm + SMM_META);
    int*   col_sh = (int*)  (sm + SMM_META + 256);
    float* xij    = (float*)(sm + SMM_META + 512);
    float* dsh    = (float*)(sm + SMM_META + 1280);
    float* sb2    = (float*)(sm + SMM_META + 1536);
    float* sb3    = (float*)(sm + SMM_META + 2048);

    if (tid < 128) sb2[tid] = b2g[tid];
    if (tid < 192) { sb3[tid * 2] = b3g[tid * 2]; sb3[tid * 2 + 1] = b3g[tid * 2 + 1]; }
    if (tid < 64) {
        int e = e0 + tid;
        int r = ei[e], c = ei[EE + e];
        row_sh[tid] = r; col_sh[tid] = c;
        float dx = coord[3 * r] - coord[3 * c];
        float dy = coord[3 * r + 1] - coord[3 * c + 1];
        float dz = coord[3 * r + 2] - coord[3 * c + 2];
        xij[3 * tid] = dx; xij[3 * tid + 1] = dy; xij[3 * tid + 2] = dz;
        dsh[tid] = sqrtf(dx * dx + dy * dy + dz * dz + 1e-8f);
    }
    __syncthreads();

    const int wm = w & 3, nh = w >> 2;
    const int gr = (wm << 4) + (l >> 2);
    const uint32_t a_lane = (((uint32_t)(2 * wm + ((l >> 3) & 1))) << 10) | (((uint32_t)(l & 7)) << 7);
    const uint32_t lmask  = ((uint32_t)(l & 7)) << 4;
    const int ak_extra = (l >> 4) << 3;
    const uint32_t b_lane = (((uint32_t)((l >> 4) & 1)) << 10) | (((uint32_t)(l & 7)) << 7);
    const uint32_t nh_off = (uint32_t)nh * 8192u;
    const int bk_extra = (l & 8);
    const int cq = 2 * (l & 3);

    float acc[8][4];
#pragma unroll
    for (int t = 0; t < 8; t++)
#pragma unroll
        for (int q = 0; q < 4; q++) acc[t][q] = 0.f;

#define RUN4(ACC, APAN, ALOFF) do { \
    _Pragma("unroll") \
    for (int s = 0; s < 4; s++) { \
        int kb = s << 4; \
        uint32_t aHi = sb + (APAN) + a_lane + ((((uint32_t)(kb + ak_extra)) << 1) ^ lmask); \
        uint32_t bHi = sb + SMM_B + b_lane + nh_off + ((((uint32_t)(kb + bk_extra)) << 1) ^ lmask); \
        uint32_t ah[4], al[4]; \
        ldsm4(ah, aHi); ldsm4(al, aHi + (ALOFF)); \
        _Pragma("unroll") \
        for (int np = 0; np < 4; np++) { \
            uint32_t bh[4], bl[4]; \
            ldsm4(bh, bHi + ((uint32_t)np << 11)); \
            ldsm4(bl, bHi + 16384u + ((uint32_t)np << 11)); \
            mma16816((ACC)[2 * np],     ah, bh[0], bh[1]); \
            mma16816((ACC)[2 * np],     al, bh[0], bh[1]); \
            mma16816((ACC)[2 * np],     ah, bl[0], bl[1]); \
            mma16816((ACC)[2 * np + 1], ah, bh[2], bh[3]); \
            mma16816((ACC)[2 * np + 1], al, bh[2], bh[3]); \
            mma16816((ACC)[2 * np + 1], ah, bl[2], bl[3]); \
        } \
    } } while (0)

#define COPYB(goff) do { \
    const unsigned char* _s = g_wimg + (goff); \
    for (int _i = tid; _i < 2048; _i += 256) \
        CPA16(sb + SMM_B + ((uint32_t)_i << 4), _s + ((size_t)_i << 4)); \
    CPA_COMMIT(); } while (0)

    // ---------------- Layer 1: K=448, 7 panels ----------------
    {
        const int ee = tid & 63, quarter = tid >> 6;
        const int rr = row_sh[ee], cc = col_sh[ee];
        const int rot = (ee >> 3) & 3;
        for (int p = 0; p < 7; p++) {
            COPYB((size_t)p * 32768u);
#pragma unroll
            for (int jj = 0; jj < 2; jj++) {
                int j = ((quarter * 2 + jj) + rot * 2) & 7;
                int kl = 8 * j;
                float v[8];
                if (p < 4) {
                    int node = (p < 2) ? rr : cc;
                    int base = 64 * (p & 1) + kl;
                    float4 a4 = *(const float4*)&h[(size_t)node * HID + base];
                    float4 b4 = *(const float4*)&h[(size_t)node * HID + base + 4];
                    v[0]=a4.x; v[1]=a4.y; v[2]=a4.z; v[3]=a4.w;
                    v[4]=b4.x; v[5]=b4.y; v[6]=b4.z; v[7]=b4.w;
                } else if (p < 6) {
                    int base = 64 * (p - 4) + kl;
#pragma unroll
                    for (int q = 0; q < 8; q++) v[q] = 0.f;
#pragma unroll
                    for (int vv = 0; vv < 3; vv++) {
                        const float* p1 = &g_v1[((size_t)rr * 3 + vv) * HID + base];
                        const float* p2 = &g_v2[((size_t)cc * 3 + vv) * HID + base];
                        float4 a4 = *(const float4*)p1, a5 = *(const float4*)(p1 + 4);
                        float4 c4 = *(const float4*)p2, c5 = *(const float4*)(p2 + 4);
                        v[0]+=a4.x*c4.x; v[1]+=a4.y*c4.y; v[2]+=a4.z*c4.z; v[3]+=a4.w*c4.w;
                        v[4]+=a5.x*c5.x; v[5]+=a5.y*c5.y; v[6]+=a5.z*c5.z; v[7]+=a5.w*c5.w;
                    }
                } else {
                    float dd = dsh[ee];
#pragma unroll
                    for (int q = 0; q < 8; q++) {
                        int kk = kl + q;
                        if (kk < 32) { float t0 = dd - (5.f / 31.f) * kk; v[q] = __expf(RBF_COEFF * t0 * t0); }
                        else if (kk < 48) v[q] = eattr[(size_t)(e0 + ee) * 16 + (kk - 32)];
                        else v[q] = (kk == 48) ? 1.f : 0.f;
                    }
                }
                uint32_t hh[4], ll[4];
#pragma unroll
                for (int m = 0; m < 4; m++) {
                    unsigned short h1, l1, h2, l2;
                    hilo(v[2 * m], h1, l1); hilo(v[2 * m + 1], h2, l2);
                    hh[m] = (uint32_t)h1 | ((uint32_t)h2 << 16);
                    ll[m] = (uint32_t)l1 | ((uint32_t)l2 << 16);
                }
                uint32_t off = amap(ee, kl);
                *(uint4*)(sm + SMM_A + off)         = make_uint4(hh[0], hh[1], hh[2], hh[3]);
                *(uint4*)(sm + SMM_A + 8192u + off) = make_uint4(ll[0], ll[1], ll[2], ll[3]);
            }
            CPA_WAIT0();
            __syncthreads();
            RUN4(acc, SMM_A, 8192u);
            __syncthreads();
        }
    }
    // epilogue 1
#pragma unroll
    for (int nt = 0; nt < 8; nt++) {
        int col = 64 * nh + 8 * nt + cq;
        uint32_t pan = (col >= 64) ? 8192u : 0u;
        uint32_t ko = (uint32_t)(col & 63);
#pragma unroll
        for (int hf = 0; hf < 2; hf++) {
            int row = gr + 8 * hf;
            float z0 = acc[nt][2 * hf], z1 = acc[nt][2 * hf + 1];
            z0 = z0 / (1.f + __expf(-z0));
            z1 = z1 / (1.f + __expf(-z1));
            unsigned short h0, l0, h1, l1;
            hilo(z0, h0, l0); hilo(z1, h1, l1);
            uint32_t off = pan + amap(row, ko);
            *(uint32_t*)(sm + SMM_C + off)          = (uint32_t)h0 | ((uint32_t)h1 << 16);
            *(uint32_t*)(sm + SMM_C + 16384u + off) = (uint32_t)l0 | ((uint32_t)l1 << 16);
        }
    }
    __syncthreads();

    // ---------------- Layer 2 ----------------
#pragma unroll
    for (int t = 0; t < 8; t++)
#pragma unroll
        for (int q = 0; q < 4; q++) acc[t][q] = 0.f;
    for (int q = 0; q < 2; q++) {
        COPYB(IMG_B2 + (size_t)q * 32768u);
        CPA_WAIT0();
        __syncthreads();
        RUN4(acc, SMM_C + (uint32_t)q * 8192u, 16384u);
        __syncthreads();
    }
    // epilogue 2
#pragma unroll
    for (int nt = 0; nt < 8; nt++) {
        int col = 64 * nh + 8 * nt + cq;
        uint32_t pan = (col >= 64) ? 8192u : 0u;
        uint32_t ko = (uint32_t)(col & 63);
        float bb0 = sb2[col], bb1 = sb2[col + 1];
#pragma unroll
        for (int hf = 0; hf < 2; hf++) {
            int row = gr + 8 * hf;
            float z0 = acc[nt][2 * hf] + bb0, z1 = acc[nt][2 * hf + 1] + bb1;
            z0 = z0 / (1.f + __expf(-z0));
            z1 = z1 / (1.f + __expf(-z1));
            unsigned short h0, l0, h1, l1;
            hilo(z0, h0, l0); hilo(z1, h1, l1);
            uint32_t off = pan + amap(row, ko);
            *(uint32_t*)(sm + SMM_C + off)          = (uint32_t)h0 | ((uint32_t)h1 << 16);
            *(uint32_t*)(sm + SMM_C + 16384u + off) = (uint32_t)l0 | ((uint32_t)l1 << 16);
        }
    }
    __syncthreads();

    // ---------------- Layer 3 ----------------
    {
        float acx[8][4];
#pragma unroll
        for (int t = 0; t < 8; t++)
#pragma unroll
            for (int q = 0; q < 4; q++) acx[t][q] = 0.f;
        for (int q = 0; q < 2; q++) {
            COPYB(IMG_B3 + (size_t)(4 + q) * 32768u);
            CPA_WAIT0();
            __syncthreads();
            RUN4(acx, SMM_C + (uint32_t)q * 8192u, 16384u);
            __syncthreads();
        }
#pragma unroll
        for (int t = 0; t < 8; t++)
#pragma unroll
            for (int q = 0; q < 4; q++) acc[t][q] = 0.f;
        for (int q = 0; q < 2; q++) {
            COPYB(IMG_B3 + (size_t)(2 + q) * 32768u);
            CPA_WAIT0();
            __syncthreads();
            RUN4(acc, SMM_C + (uint32_t)q * 8192u, 16384u);
            __syncthreads();
        }
#pragma unroll
        for (int nt = 0; nt < 8; nt++) {
            int col = 64 * nh + 8 * nt + cq;
#pragma unroll
            for (int hf = 0; hf < 2; hf++) {
                acx[nt][2 * hf]     += sb3[256 + col];
                acx[nt][2 * hf + 1] += sb3[256 + col + 1];
                acc[nt][2 * hf]     += sb3[128 + col];
                acc[nt][2 * hf + 1] += sb3[128 + col + 1];
            }
        }
#pragma unroll 1
        for (int hf = 0; hf < 2; hf++) {
            int er = gr + 8 * hf;
            int ro = row_sh[er], co = col_sh[er];
            float x0 = xij[3 * er], x1 = xij[3 * er + 1], x2 = xij[3 * er + 2];
#pragma unroll 1
            for (int v = 0; v < 3; v++) {
                float xv = (v == 0) ? x0 : (v == 1) ? x1 : x2;
                const float* vbp = &g_v3[((size_t)co * 3 + v) * HID];
                float* abp = &g_vaggr[((size_t)ro * 3 + v) * HID];
#pragma unroll
                for (int nt = 0; nt < 8; nt++) {
                    int c0 = 64 * nh + 8 * nt + cq;
                    float2 v3v = *(const float2*)(vbp + c0);
                    RED2(abp + c0,
                         v3v.x * acc[nt][2 * hf]     + acx[nt][2 * hf]     * xv,
                         v3v.y * acc[nt][2 * hf + 1] + acx[nt][2 * hf + 1] * xv);
                }
            }
        }
#pragma unroll
        for (int t = 0; t < 8; t++)
#pragma unroll
            for (int q = 0; q < 4; q++) acx[t][q] = 0.f;
        for (int q = 0; q < 2; q++) {
            COPYB(IMG_B3 + (size_t)q * 32768u);
            CPA_WAIT0();
            __syncthreads();
            RUN4(acx, SMM_C + (uint32_t)q * 8192u, 16384u);
            __syncthreads();
        }
#pragma unroll 1
        for (int hf = 0; hf < 2; hf++) {
            int er = gr + 8 * hf;
            int ro = row_sh[er];
            float* hbp = &g_haggr[(size_t)ro * HID];
#pragma unroll
            for (int nt = 0; nt < 8; nt++) {
                int c0 = 64 * nh + 8 * nt + cq;
                RED2(hbp + c0,
                     acx[nt][2 * hf]     + sb3[c0],
                     acx[nt][2 * hf + 1] + sb3[c0 + 1]);
            }
        }
    }
#undef RUN4
#undef COPYB
}

// ======================= launch =======================
extern "C" void kernel_launch(void* const* d_in, const int* in_sizes, int n_in,
                              void* d_out, int out_size) {
    const float* h     = (const float*)d_in[0];
    const float* vec   = (const float*)d_in[1];
    const float* coord = (const float*)d_in[2];
    const int*   ei    = (const int*)  d_in[3];
    const float* eattr = (const float*)d_in[4];
    const float* Wvp   = (const float*)d_in[5];
    const float* W1    = (const float*)d_in[6];
    const float* b1    = (const float*)d_in[7];
    const float* W2    = (const float*)d_in[8];
    const float* b2    = (const float*)d_in[9];
    const float* W3    = (const float*)d_in[10];
    const float* b3    = (const float*)d_in[11];
    const float* Wop   = (const float*)d_in[12];
    const float* bop   = (const float*)d_in[13];
    float* out = (float*)d_out;

    cudaFuncSetAttribute(k_edge_m, cudaFuncAttributeMaxDynamicSharedMemorySize, SMM_TOT);
    cudaFuncSetAttribute(k_gemm,   cudaFuncAttributeMaxDynamicSharedMemorySize, GM_TOT);

    k_prep<<<864, 256>>>(W1, b1, W2, W3, Wvp, Wop);
    k_zero<<<25000, 256>>>();
    k_gemm<<<2344, 256, GM_TOT>>>(vec, 3 * NN, IMG_BVP, 0);           // vecp -> v1/v2/v3
    k_edge_m<<<EE / 64, 256, SMM_TOT>>>(h, coord, ei, eattr, b2, b3);
    k_gemm<<<782, 256, GM_TOT>>>(nullptr, NN, IMG_BOP, 1);            // h_aggr @ Wop -> g_o
    k_final<<<NN * 32 / 256, 256>>>(bop, out);
}

// round 12
// speedup vs baseline: 1.5530x; 1.0764x over previous
#include <cuda_runtime.h>
#include <cuda_bf16.h>
#include <math.h>
#include <stdint.h>

#define NN    50000
#define EE    400000
#define HID   128
#define RBF_COEFF (-19.22f)

// ---------------- scratch ----------------
__device__ float g_v1[(size_t)NN * 3 * HID];
__device__ float g_v2[(size_t)NN * 3 * HID];
__device__ float g_v3[(size_t)NN * 3 * HID];
__device__ float g_haggr[(size_t)NN * HID];
__device__ float g_vaggr[(size_t)NN * 3 * HID];
__device__ float g_o[(size_t)NN * 384];
// weight image: panel-pairs [hi 16KB | lo 16KB], [n=128][k=64] bf16, SW128 swizzle
__device__ __align__(16) unsigned char g_wimg[884736];
#define IMG_B2  229376u
#define IMG_B3  294912u
#define IMG_BVP 491520u
#define IMG_BOP 688128u

// ---------------- helpers ----------------
__device__ __forceinline__ uint32_t smem_u32(const void* p) {
    uint32_t a;
    asm("{ .reg .u64 t; cvta.to.shared.u64 t, %1; cvt.u32.u64 %0, t; }" : "=r"(a) : "l"(p));
    return a;
}
__device__ __forceinline__ uint32_t amap(int m, int k) {
    return (((uint32_t)(m >> 3)) << 10) + (((uint32_t)(m & 7)) << 7)
         + ((((uint32_t)k << 1)) ^ (((uint32_t)(m & 7)) << 4));
}
__device__ __forceinline__ void hilo(float v, unsigned short& hi, unsigned short& lo) {
    __nv_bfloat16 h = __float2bfloat16(v);
    hi = __bfloat16_as_ushort(h);
    lo = __bfloat16_as_ushort(__float2bfloat16(v - __bfloat162float(h)));
}
__device__ __forceinline__ void ldsm4(uint32_t r[4], uint32_t addr) {
    asm volatile("ldmatrix.sync.aligned.m8n8.x4.shared.b16 {%0,%1,%2,%3}, [%4];"
        : "=r"(r[0]), "=r"(r[1]), "=r"(r[2]), "=r"(r[3]) : "r"(addr));
}
__device__ __forceinline__ void mma16816(float c[4], const uint32_t a[4], uint32_t b0, uint32_t b1) {
    asm volatile("mma.sync.aligned.m16n8k16.row.col.f32.bf16.bf16.f32 "
        "{%0,%1,%2,%3}, {%4,%5,%6,%7}, {%8,%9}, {%0,%1,%2,%3};"
        : "+f"(c[0]), "+f"(c[1]), "+f"(c[2]), "+f"(c[3])
        : "r"(a[0]), "r"(a[1]), "r"(a[2]), "r"(a[3]), "r"(b0), "r"(b1));
}
#define RED2(p, a, b) \
    asm volatile("red.global.add.v2.f32 [%0], {%1,%2};" :: "l"(p), "f"(a), "f"(b) : "memory")
#define CPA16(sa, gp) asm volatile("cp.async.cg.shared.global [%0], [%1], 16;" :: "r"(sa), "l"(gp))
#define CPA_COMMIT()  asm volatile("cp.async.commit_group;" ::: "memory")
#define CPA_WAIT0()   asm volatile("cp.async.wait_group 0;" ::: "memory")
#define CPA_WAIT1()   asm volatile("cp.async.wait_group 1;" ::: "memory")

// ======================= weight prep =======================
__global__ void k_prep(const float* __restrict__ W1, const float* __restrict__ b1,
                       const float* __restrict__ W2, const float* __restrict__ W3,
                       const float* __restrict__ Wvp, const float* __restrict__ Wop) {
    int idx = blockIdx.x * 256 + threadIdx.x;
    if (idx >= 221184) return;
    float v; uint32_t off;
    if (idx < 57344) {                       // L1 K-order: h_row|h_col|cross|rbf|ea|bias|0
        int k = idx >> 7, n = idx & 127;
        if      (k < 256)  v = W1[(size_t)k * HID + n];
        else if (k < 384)  v = W1[(size_t)(k + 32) * HID + n];
        else if (k < 416)  v = W1[(size_t)(k - 128) * HID + n];
        else if (k < 432)  v = W1[(size_t)k * HID + n];
        else if (k == 432) v = b1[n];
        else               v = 0.f;
        off = (uint32_t)(k >> 6) * 32768u + amap(n, k & 63);
    } else if (idx < 73728) {                // L2
        int i2 = idx - 57344, k = i2 >> 7, n = i2 & 127;
        v = W2[(size_t)k * HID + n];
        off = IMG_B2 + (uint32_t)(k >> 6) * 32768u + amap(n, k & 63);
    } else if (idx < 122880) {               // L3 tile t
        int i3 = idx - 73728, t = i3 >> 14, rem = i3 & 16383, k = rem >> 7, n = rem & 127;
        v = W3[(size_t)k * 384 + 128 * t + n];
        off = IMG_B3 + (uint32_t)(t * 2 + (k >> 6)) * 32768u + amap(n, k & 63);
    } else if (idx < 172032) {               // Wvp tile t
        int i4 = idx - 122880, t = i4 >> 14, rem = i4 & 16383, k = rem >> 7, n = rem & 127;
        v = Wvp[(size_t)k * 384 + 128 * t + n];
        off = IMG_BVP + (uint32_t)(t * 2 + (k >> 6)) * 32768u + amap(n, k & 63);
    } else {                                 // Wop tile t
        int i5 = idx - 172032, t = i5 >> 14, rem = i5 & 16383, k = rem >> 7, n = rem & 127;
        v = Wop[(size_t)k * 384 + 128 * t + n];
        off = IMG_BOP + (uint32_t)(t * 2 + (k >> 6)) * 32768u + amap(n, k & 63);
    }
    unsigned short hi, lo; hilo(v, hi, lo);
    *(unsigned short*)(g_wimg + off)         = hi;
    *(unsigned short*)(g_wimg + off + 16384) = lo;
}

// ======================= zero =======================
__global__ void k_zero() {
    int i = blockIdx.x * blockDim.x + threadIdx.x;
    const int n1 = NN * HID / 4;
    float4 z = make_float4(0.f, 0.f, 0.f, 0.f);
    if (i < n1) reinterpret_cast<float4*>(g_haggr)[i] = z;
    else        reinterpret_cast<float4*>(g_vaggr)[i - n1] = z;
}

// ======================= generic 64-row GEMM: src[M,128] @ W[128,384] =======================
#define GM_A 0u          // hi q*8192 ; lo 16384 + q*8192
#define GM_B 32768u      // 2 x 32KB ping-pong
#define GM_TOT 98304

__global__ void __launch_bounds__(256, 2) k_gemm(const float* __restrict__ srcp,
                                                 int Mtot, uint32_t wbase, int mode) {
    extern __shared__ __align__(1024) unsigned char sm[];
    const int tid = threadIdx.x, w = tid >> 5, l = tid & 31;
    const int r0 = blockIdx.x * 64;
    const uint32_t sb = smem_u32(sm);
    const float* src = (mode == 0) ? srcp : g_haggr;

#define GCOPYB(goff, s) do { \
    const unsigned char* _s = g_wimg + (goff); \
    uint32_t _d = sb + GM_B + (uint32_t)(s) * 32768u; \
    for (int _i = tid; _i < 2048; _i += 256) \
        CPA16(_d + ((uint32_t)_i << 4), _s + ((size_t)_i << 4)); \
    CPA_COMMIT(); } while (0)

    GCOPYB(wbase, 0);

    // build A: 64 rows x 128 K, hi/lo, coalesced (16 lanes per row-segment)
    {
        const int eb = (w << 1) + (l >> 4);     // row within 16-row pass group
        const int hl = l & 15;                  // 16B chunk (cols 4hl..4hl+3)
#pragma unroll 1
        for (int pass = 0; pass < 4; pass++) {
            int e = pass * 16 + eb;
            int rg = r0 + e;
            bool valid = rg < Mtot;
#pragma unroll
            for (int qp = 0; qp < 2; qp++) {
                float4 v4 = make_float4(0.f, 0.f, 0.f, 0.f);
                if (valid) v4 = *(const float4*)&src[(size_t)rg * 128 + qp * 64 + 4 * hl];
                unsigned short h0, l0, h1, l1, h2, l2, h3, l3;
                hilo(v4.x, h0, l0); hilo(v4.y, h1, l1);
                hilo(v4.z, h2, l2); hilo(v4.w, h3, l3);
                uint32_t off = (uint32_t)qp * 8192u + amap(e, 4 * hl);
                *(uint2*)(sm + GM_A + off) =
                    make_uint2((uint32_t)h0 | ((uint32_t)h1 << 16), (uint32_t)h2 | ((uint32_t)h3 << 16));
                *(uint2*)(sm + GM_A + 16384u + off) =
                    make_uint2((uint32_t)l0 | ((uint32_t)l1 << 16), (uint32_t)l2 | ((uint32_t)l3 << 16));
            }
        }
    }

    const int wm = w & 3, nh = w >> 2;
    const int gr = (wm << 4) + (l >> 2);
    const uint32_t a_lane = (((uint32_t)(2 * wm + ((l >> 3) & 1))) << 10) | (((uint32_t)(l & 7)) << 7);
    const uint32_t lmask  = ((uint32_t)(l & 7)) << 4;
    const int ak_extra = (l >> 4) << 3;
    const uint32_t b_lane = (((uint32_t)((l >> 4) & 1)) << 10) | (((uint32_t)(l & 7)) << 7);
    const uint32_t nh_off = (uint32_t)nh * 8192u;
    const int bk_extra = (l & 8);
    const int cq = 2 * (l & 3);

#define GRUN4(ACC, APAN, BUF) do { \
    uint32_t _bb = sb + GM_B + (uint32_t)(BUF) * 32768u; \
    _Pragma("unroll") \
    for (int s = 0; s < 4; s++) { \
        int kb = s << 4; \
        uint32_t aHi = sb + (APAN) + a_lane + ((((uint32_t)(kb + ak_extra)) << 1) ^ lmask); \
        uint32_t bHi = _bb + b_lane + nh_off + ((((uint32_t)(kb + bk_extra)) << 1) ^ lmask); \
        uint32_t ah[4], al[4]; \
        ldsm4(ah, aHi); ldsm4(al, aHi + 16384u); \
        _Pragma("unroll") \
        for (int np = 0; np < 4; np++) { \
            uint32_t bh[4], bl[4]; \
            ldsm4(bh, bHi + ((uint32_t)np << 11)); \
            ldsm4(bl, bHi + 16384u + ((uint32_t)np << 11)); \
            mma16816((ACC)[2 * np],     ah, bh[0], bh[1]); \
            mma16816((ACC)[2 * np],     al, bh[0], bh[1]); \
            mma16816((ACC)[2 * np],     ah, bl[0], bl[1]); \
            mma16816((ACC)[2 * np + 1], ah, bh[2], bh[3]); \
            mma16816((ACC)[2 * np + 1], al, bh[2], bh[3]); \
            mma16816((ACC)[2 * np + 1], ah, bl[2], bl[3]); \
        } \
    } } while (0)

    float acc[8][4];
    for (int t = 0; t < 3; t++) {
#pragma unroll
        for (int nt = 0; nt < 8; nt++)
#pragma unroll
            for (int q = 0; q < 4; q++) acc[nt][q] = 0.f;
        for (int q = 0; q < 2; q++) {
            int i = t * 2 + q;
            if (i < 5) { GCOPYB(wbase + (uint32_t)(i + 1) * 32768u, (i + 1) & 1); CPA_WAIT1(); }
            else CPA_WAIT0();
            __syncthreads();
            GRUN4(acc, GM_A + (uint32_t)q * 8192u, i & 1);
            __syncthreads();
        }
#pragma unroll
        for (int nt = 0; nt < 8; nt++) {
            int col = 64 * nh + 8 * nt + cq;
#pragma unroll
            for (int hf = 0; hf < 2; hf++) {
                int rg = r0 + gr + 8 * hf;
                if (rg < Mtot) {
                    float* p;
                    if (mode == 0) p = ((t == 0) ? g_v1 : (t == 1) ? g_v2 : g_v3) + (size_t)rg * 128 + col;
                    else           p = g_o + (size_t)rg * 384 + 128 * t + col;
                    *(float2*)p = make_float2(acc[nt][2 * hf], acc[nt][2 * hf + 1]);
                }
            }
        }
    }
#undef GRUN4
#undef GCOPYB
}

// ======================= final elementwise: dh, dvec (+vdot) =======================
__global__ __launch_bounds__(256) void k_final(const float* __restrict__ bop,
                                               float* __restrict__ out) {
    int g = blockIdx.x * 256 + threadIdx.x;           // 50000*32
    int n = g >> 5, c = (g & 31) * 4;
    const float* op = g_o + (size_t)n * 384;
    float4 o1 = *(const float4*)&op[c];
    float4 o2 = *(const float4*)&op[128 + c];
    float4 o3 = *(const float4*)&op[256 + c];
    float4 b1v = *(const float4*)&bop[c];
    float4 b2v = *(const float4*)&bop[128 + c];
    float4 b3v = *(const float4*)&bop[256 + c];
    o1.x += b1v.x; o1.y += b1v.y; o1.z += b1v.z; o1.w += b1v.w;
    o2.x += b2v.x; o2.y += b2v.y; o2.z += b2v.z; o2.w += b2v.w;
    o3.x += b3v.x; o3.y += b3v.y; o3.z += b3v.z; o3.w += b3v.w;
    float vd[4] = {0.f, 0.f, 0.f, 0.f};
#pragma unroll
    for (int v = 0; v < 3; v++) {
        size_t base = ((size_t)n * 3 + v) * 128 + c;
        float4 a = *(const float4*)&g_v1[base];
        float4 b = *(const float4*)&g_v2[base];
        vd[0] += a.x * b.x; vd[1] += a.y * b.y; vd[2] += a.z * b.z; vd[3] += a.w * b.w;
    }
    *(float4*)&out[(size_t)n * 128 + c] =
        make_float4(vd[0] * o2.x + o3.x, vd[1] * o2.y + o3.y,
                    vd[2] * o2.z + o3.z, vd[3] * o2.w + o3.w);
#pragma unroll
    for (int v = 0; v < 3; v++) {
        size_t base = ((size_t)n * 3 + v) * 128 + c;
        float4 v3 = *(const float4*)&g_v3[base];
        float4 va = *(const float4*)&g_vaggr[base];
        *(float4*)&out[(size_t)NN * 128 + base] =
            make_float4(v3.x * o1.x + va.x, v3.y * o1.y + va.y,
                        v3.z * o1.z + va.z, v3.w * o1.w + va.w);
    }
}

// ======================= tensorized edge kernel (64 edges/CTA, 2 CTA/SM) =======================
#define SMM_A 0u
#define SMM_C 16384u
#define SMM_B 49152u
#define SMM_META 81920u
#define SMM_TOT  86016

__global__ void __launch_bounds__(256, 2) k_edge_m(const float* __restrict__ h,
                                                   const float* __restrict__ coord,
                                                   const int*   __restrict__ ei,
                                                   const float* __restrict__ eattr,
                                                   const float* __restrict__ b2g,
                                                   const float* __restrict__ b3g) {
    extern __shared__ __align__(1024) unsigned char sm[];
    const int tid = threadIdx.x, w = tid >> 5, l = tid & 31;
    const int e0 = blockIdx.x * 64;
    const uint32_t sb = smem_u32(sm);
    int*   row_sh = (int*)  (sm + SMM_META);
    int*   col_sh = (int*)  (sm + SMM_META + 256);
    float* xij    = (float*)(sm + SMM_META + 512);
    float* dsh    = (float*)(sm + SMM_META + 1280);
    float* sb2    = (float*)(sm + SMM_META + 1536);
    float* sb3    = (float*)(sm + SMM_META + 2048);

    if (tid < 128) sb2[tid] = b2g[tid];
    if (tid < 192) { sb3[tid * 2] = b3g[tid * 2]; sb3[tid * 2 + 1] = b3g[tid * 2 + 1]; }
    if (tid < 64) {
        int e = e0 + tid;
        int r = ei[e], c = ei[EE + e];
        row_sh[tid] = r; col_sh[tid] = c;
        float dx = coord[3 * r] - coord[3 * c];
        float dy = coord[3 * r + 1] - coord[3 * c + 1];
        float dz = coord[3 * r + 2] - coord[3 * c + 2];
        xij[3 * tid] = dx; xij[3 * tid + 1] = dy; xij[3 * tid + 2] = dz;
        dsh[tid] = sqrtf(dx * dx + dy * dy + dz * dz + 1e-8f);
    }
    __syncthreads();

    const int wm = w & 3, nh = w >> 2;
    const int gr = (wm << 4) + (l >> 2);
    const uint32_t a_lane = (((uint32_t)(2 * wm + ((l >> 3) & 1))) << 10) | (((uint32_t)(l & 7)) << 7);
    const uint32_t lmask  = ((uint32_t)(l & 7)) << 4;
    const int ak_extra = (l >> 4) << 3;
    const uint32_t b_lane = (((uint32_t)((l >> 4) & 1)) << 10) | (((uint32_t)(l & 7)) << 7);
    const uint32_t nh_off = (uint32_t)nh * 8192u;
    const int bk_extra = (l & 8);
    const int cq = 2 * (l & 3);

    float acc[8][4];
#pragma unroll
    for (int t = 0; t < 8; t++)
#pragma unroll
        for (int q = 0; q < 4; q++) acc[t][q] = 0.f;

#define RUN4(ACC, APAN, ALOFF) do { \
    _Pragma("unroll") \
    for (int s = 0; s < 4; s++) { \
        int kb = s << 4; \
        uint32_t aHi = sb + (APAN) + a_lane + ((((uint32_t)(kb + ak_extra)) << 1) ^ lmask); \
        uint32_t bHi = sb + SMM_B + b_lane + nh_off + ((((uint32_t)(kb + bk_extra)) << 1) ^ lmask); \
        uint32_t ah[4], al[4]; \
        ldsm4(ah, aHi); ldsm4(al, aHi + (ALOFF)); \
        _Pragma("unroll") \
        for (int np = 0; np < 4; np++) { \
            uint32_t bh[4], bl[4]; \
            ldsm4(bh, bHi + ((uint32_t)np << 11)); \
            ldsm4(bl, bHi + 16384u + ((uint32_t)np << 11)); \
            mma16816((ACC)[2 * np],     ah, bh[0], bh[1]); \
            mma16816((ACC)[2 * np],     al, bh[0], bh[1]); \
            mma16816((ACC)[2 * np],     ah, bl[0], bl[1]); \
            mma16816((ACC)[2 * np + 1], ah, bh[2], bh[3]); \
            mma16816((ACC)[2 * np + 1], al, bh[2], bh[3]); \
            mma16816((ACC)[2 * np + 1], ah, bl[2], bl[3]); \
        } \
    } } while (0)

#define COPYB(goff) do { \
    const unsigned char* _s = g_wimg + (goff); \
    for (int _i = tid; _i < 2048; _i += 256) \
        CPA16(sb + SMM_B + ((uint32_t)_i << 4), _s + ((size_t)_i << 4)); \
    CPA_COMMIT(); } while (0)

    // ---------------- Layer 1: K=448, 7 panels, COALESCED build ----------------
    {
        const int eb = (w << 1) + (l >> 4);     // edge within 16-edge pass group
        const int hl = l & 15;                  // 16B chunk: cols 4hl..4hl+3
        for (int p = 0; p < 7; p++) {
            COPYB((size_t)p * 32768u);
#pragma unroll 1
            for (int pass = 0; pass < 4; pass++) {
                int e = pass * 16 + eb;
                float4 v4;
                if (p < 4) {
                    int node = (p < 2) ? row_sh[e] : col_sh[e];
                    v4 = *(const float4*)&h[(size_t)node * HID + 64 * (p & 1) + 4 * hl];
                } else if (p < 6) {
                    int rr = row_sh[e], cc = col_sh[e];
                    int base = 64 * (p - 4) + 4 * hl;
                    v4 = make_float4(0.f, 0.f, 0.f, 0.f);
#pragma unroll
                    for (int vv = 0; vv < 3; vv++) {
                        float4 a4 = *(const float4*)&g_v1[((size_t)rr * 3 + vv) * HID + base];
                        float4 c4 = *(const float4*)&g_v2[((size_t)cc * 3 + vv) * HID + base];
                        v4.x += a4.x * c4.x; v4.y += a4.y * c4.y;
                        v4.z += a4.z * c4.z; v4.w += a4.w * c4.w;
                    }
                } else {
                    float dd = dsh[e];
                    float vv[4];
#pragma unroll
                    for (int q = 0; q < 4; q++) {
                        int kk = 4 * hl + q;
                        if (kk < 32) { float t0 = dd - (5.f / 31.f) * kk; vv[q] = __expf(RBF_COEFF * t0 * t0); }
                        else vv[q] = (kk == 48) ? 1.f : 0.f;
                    }
                    if (hl >= 8 && hl < 12) {
                        float4 ea = *(const float4*)&eattr[(size_t)(e0 + e) * 16 + (4 * hl - 32)];
                        vv[0] = ea.x; vv[1] = ea.y; vv[2] = ea.z; vv[3] = ea.w;
                    }
                    v4 = make_float4(vv[0], vv[1], vv[2], vv[3]);
                }
                unsigned short h0, l0, h1, l1, h2, l2, h3, l3;
                hilo(v4.x, h0, l0); hilo(v4.y, h1, l1);
                hilo(v4.z, h2, l2); hilo(v4.w, h3, l3);
                uint32_t off = amap(e, 4 * hl);
                *(uint2*)(sm + SMM_A + off) =
                    make_uint2((uint32_t)h0 | ((uint32_t)h1 << 16), (uint32_t)h2 | ((uint32_t)h3 << 16));
                *(uint2*)(sm + SMM_A + 8192u + off) =
                    make_uint2((uint32_t)l0 | ((uint32_t)l1 << 16), (uint32_t)l2 | ((uint32_t)l3 << 16));
            }
            CPA_WAIT0();
            __syncthreads();
            RUN4(acc, SMM_A, 8192u);
            __syncthreads();
        }
    }
    // epilogue 1
#pragma unroll
    for (int nt = 0; nt < 8; nt++) {
        int col = 64 * nh + 8 * nt + cq;
        uint32_t pan = (col >= 64) ? 8192u : 0u;
        uint32_t ko = (uint32_t)(col & 63);
#pragma unroll
        for (int hf = 0; hf < 2; hf++) {
            int row = gr + 8 * hf;
            float z0 = acc[nt][2 * hf], z1 = acc[nt][2 * hf + 1];
            z0 = z0 / (1.f + __expf(-z0));
            z1 = z1 / (1.f + __expf(-z1));
            unsigned short h0, l0, h1, l1;
            hilo(z0, h0, l0); hilo(z1, h1, l1);
            uint32_t off = pan + amap(row, ko);
            *(uint32_t*)(sm + SMM_C + off)          = (uint32_t)h0 | ((uint32_t)h1 << 16);
            *(uint32_t*)(sm + SMM_C + 16384u + off) = (uint32_t)l0 | ((uint32_t)l1 << 16);
        }
    }
    __syncthreads();

    // ---------------- Layer 2 ----------------
#pragma unroll
    for (int t = 0; t < 8; t++)
#pragma unroll
        for (int q = 0; q < 4; q++) acc[t][q] = 0.f;
    for (int q = 0; q < 2; q++) {
        COPYB(IMG_B2 + (size_t)q * 32768u);
        CPA_WAIT0();
        __syncthreads();
        RUN4(acc, SMM_C + (uint32_t)q * 8192u, 16384u);
        __syncthreads();
    }
    // epilogue 2
#pragma unroll
    for (int nt = 0; nt < 8; nt++) {
        int col = 64 * nh + 8 * nt + cq;
        uint32_t pan = (col >= 64) ? 8192u : 0u;
        uint32_t ko = (uint32_t)(col & 63);
        float bb0 = sb2[col], bb1 = sb2[col + 1];
#pragma unroll
        for (int hf = 0; hf < 2; hf++) {
            int row = gr + 8 * hf;
            float z0 = acc[nt][2 * hf] + bb0, z1 = acc[nt][2 * hf + 1] + bb1;
            z0 = z0 / (1.f + __expf(-z0));
            z1 = z1 / (1.f + __expf(-z1));
            unsigned short h0, l0, h1, l1;
            hilo(z0, h0, l0); hilo(z1, h1, l1);
            uint32_t off = pan + amap(row, ko);
            *(uint32_t*)(sm + SMM_C + off)          = (uint32_t)h0 | ((uint32_t)h1 << 16);
            *(uint32_t*)(sm + SMM_C + 16384u + off) = (uint32_t)l0 | ((uint32_t)l1 << 16);
        }
    }
    __syncthreads();

    // ---------------- Layer 3 ----------------
    {
        float acx[8][4];
#pragma unroll
        for (int t = 0; t < 8; t++)
#pragma unroll
            for (int q = 0; q < 4; q++) acx[t][q] = 0.f;
        for (int q = 0; q < 2; q++) {
            COPYB(IMG_B3 + (size_t)(4 + q) * 32768u);
            CPA_WAIT0();
            __syncthreads();
            RUN4(acx, SMM_C + (uint32_t)q * 8192u, 16384u);
            __syncthreads();
        }
#pragma unroll
        for (int t = 0; t < 8; t++)
#pragma unroll
            for (int q = 0; q < 4; q++) acc[t][q] = 0.f;
        for (int q = 0; q < 2; q++) {
            COPYB(IMG_B3 + (size_t)(2 + q) * 32768u);
            CPA_WAIT0();
            __syncthreads();
            RUN4(acc, SMM_C + (uint32_t)q * 8192u, 16384u);
            __syncthreads();
        }
#pragma unroll
        for (int nt = 0; nt < 8; nt++) {
            int col = 64 * nh + 8 * nt + cq;
#pragma unroll
            for (int hf = 0; hf < 2; hf++) {
                acx[nt][2 * hf]     += sb3[256 + col];
                acx[nt][2 * hf + 1] += sb3[256 + col + 1];
                acc[nt][2 * hf]     += sb3[128 + col];
                acc[nt][2 * hf + 1] += sb3[128 + col + 1];
            }
        }
#pragma unroll 1
        for (int hf = 0; hf < 2; hf++) {
            int er = gr + 8 * hf;
            int ro = row_sh[er], co = col_sh[er];
            float x0 = xij[3 * er], x1 = xij[3 * er + 1], x2 = xij[3 * er + 2];
#pragma unroll 1
            for (int v = 0; v < 3; v++) {
                float xv = (v == 0) ? x0 : (v == 1) ? x1 : x2;
                const float* vbp = &g_v3[((size_t)co * 3 + v) * HID];
                float* abp = &g_vaggr[((size_t)ro * 3 + v) * HID];
#pragma unroll
                for (int nt = 0; nt < 8; nt++) {
                    int c0 = 64 * nh + 8 * nt + cq;
                    float2 v3v = *(const float2*)(vbp + c0);
                    RED2(abp + c0,
                         v3v.x * acc[nt][2 * hf]     + acx[nt][2 * hf]     * xv,
                         v3v.y * acc[nt][2 * hf + 1] + acx[nt][2 * hf + 1] * xv);
                }
            }
        }
#pragma unroll
        for (int t = 0; t < 8; t++)
#pragma unroll
            for (int q = 0; q < 4; q++) acx[t][q] = 0.f;
        for (int q = 0; q < 2; q++) {
            COPYB(IMG_B3 + (size_t)q * 32768u);
            CPA_WAIT0();
            __syncthreads();
            RUN4(acx, SMM_C + (uint32_t)q * 8192u, 16384u);
            __syncthreads();
        }
#pragma unroll 1
        for (int hf = 0; hf < 2; hf++) {
            int er = gr + 8 * hf;
            int ro = row_sh[er];
            float* hbp = &g_haggr[(size_t)ro * HID];
#pragma unroll
            for (int nt = 0; nt < 8; nt++) {
                int c0 = 64 * nh + 8 * nt + cq;
                RED2(hbp + c0,
                     acx[nt][2 * hf]     + sb3[c0],
                     acx[nt][2 * hf + 1] + sb3[c0 + 1]);
            }
        }
    }
#undef RUN4
#undef COPYB
}

// ======================= launch =======================
extern "C" void kernel_launch(void* const* d_in, const int* in_sizes, int n_in,
                              void* d_out, int out_size) {
    const float* h     = (const float*)d_in[0];
    const float* vec   = (const float*)d_in[1];
    const float* coord = (const float*)d_in[2];
    const int*   ei    = (const int*)  d_in[3];
    const float* eattr = (const float*)d_in[4];
    const float* Wvp   = (const float*)d_in[5];
    const float* W1    = (const float*)d_in[6];
    const float* b1    = (const float*)d_in[7];
    const float* W2    = (const float*)d_in[8];
    const float* b2    = (const float*)d_in[9];
    const float* W3    = (const float*)d_in[10];
    const float* b3    = (const float*)d_in[11];
    const float* Wop   = (const float*)d_in[12];
    const float* bop   = (const float*)d_in[13];
    float* out = (float*)d_out;

    cudaFuncSetAttribute(k_edge_m, cudaFuncAttributeMaxDynamicSharedMemorySize, SMM_TOT);
    cudaFuncSetAttribute(k_gemm,   cudaFuncAttributeMaxDynamicSharedMemorySize, GM_TOT);

    k_prep<<<864, 256>>>(W1, b1, W2, W3, Wvp, Wop);
    k_zero<<<25000, 256>>>();
    k_gemm<<<2344, 256, GM_TOT>>>(vec, 3 * NN, IMG_BVP, 0);           // vecp -> v1/v2/v3
    k_edge_m<<<EE / 64, 256, SMM_TOT>>>(h, coord, ei, eattr, b2, b3);
    k_gemm<<<782, 256, GM_TOT>>>(nullptr, NN, IMG_BOP, 1);            // h_aggr @ Wop -> g_o
    k_final<<<NN * 32 / 256, 256>>>(bop, out);
}

// round 13
// speedup vs baseline: 1.6551x; 1.0657x over previous
#include <cuda_runtime.h>
#include <cuda_bf16.h>
#include <math.h>
#include <stdint.h>

#define NN    50000
#define EE    400000
#define HID   128
#define RBF_COEFF (-19.22f)

// ---------------- scratch ----------------
__device__ float g_v1[(size_t)NN * 3 * HID];
__device__ float g_v2[(size_t)NN * 3 * HID];
__device__ float g_v3[(size_t)NN * 3 * HID];
__device__ float g_haggr[(size_t)NN * HID];
__device__ float g_vaggr[(size_t)NN * 3 * HID];
__device__ float g_o[(size_t)NN * 384];
// weight image: panel-pairs [hi 16KB | lo 16KB], [n=128][k=64] bf16, SW128 swizzle
__device__ __align__(16) unsigned char g_wimg[884736];
#define IMG_B2  229376u
#define IMG_B3  294912u
#define IMG_BVP 491520u
#define IMG_BOP 688128u

// ---------------- helpers ----------------
__device__ __forceinline__ uint32_t smem_u32(const void* p) {
    uint32_t a;
    asm("{ .reg .u64 t; cvta.to.shared.u64 t, %1; cvt.u32.u64 %0, t; }" : "=r"(a) : "l"(p));
    return a;
}
__device__ __forceinline__ uint32_t amap(int m, int k) {
    return (((uint32_t)(m >> 3)) << 10) + (((uint32_t)(m & 7)) << 7)
         + ((((uint32_t)k << 1)) ^ (((uint32_t)(m & 7)) << 4));
}
__device__ __forceinline__ void hilo(float v, unsigned short& hi, unsigned short& lo) {
    __nv_bfloat16 h = __float2bfloat16(v);
    hi = __bfloat16_as_ushort(h);
    lo = __bfloat16_as_ushort(__float2bfloat16(v - __bfloat162float(h)));
}
__device__ __forceinline__ void ldsm4(uint32_t r[4], uint32_t addr) {
    asm volatile("ldmatrix.sync.aligned.m8n8.x4.shared.b16 {%0,%1,%2,%3}, [%4];"
        : "=r"(r[0]), "=r"(r[1]), "=r"(r[2]), "=r"(r[3]) : "r"(addr));
}
__device__ __forceinline__ void mma16816(float c[4], const uint32_t a[4], uint32_t b0, uint32_t b1) {
    asm volatile("mma.sync.aligned.m16n8k16.row.col.f32.bf16.bf16.f32 "
        "{%0,%1,%2,%3}, {%4,%5,%6,%7}, {%8,%9}, {%0,%1,%2,%3};"
        : "+f"(c[0]), "+f"(c[1]), "+f"(c[2]), "+f"(c[3])
        : "r"(a[0]), "r"(a[1]), "r"(a[2]), "r"(a[3]), "r"(b0), "r"(b1));
}
#define RED2(p, a, b) \
    asm volatile("red.global.add.v2.f32 [%0], {%1,%2};" :: "l"(p), "f"(a), "f"(b) : "memory")
#define CPA16(sa, gp) asm volatile("cp.async.cg.shared.global [%0], [%1], 16;" :: "r"(sa), "l"(gp))
#define CPA_COMMIT()  asm volatile("cp.async.commit_group;" ::: "memory")
#define CPA_WAIT0()   asm volatile("cp.async.wait_group 0;" ::: "memory")
#define CPA_WAIT1()   asm volatile("cp.async.wait_group 1;" ::: "memory")

// ======================= weight prep =======================
__global__ void k_prep(const float* __restrict__ W1, const float* __restrict__ b1,
                       const float* __restrict__ W2, const float* __restrict__ W3,
                       const float* __restrict__ Wvp, const float* __restrict__ Wop) {
    int idx = blockIdx.x * 256 + threadIdx.x;
    if (idx >= 221184) return;
    float v; uint32_t off;
    if (idx < 57344) {                       // L1 K-order: h_row|h_col|cross|rbf|ea|bias|0
        int k = idx >> 7, n = idx & 127;
        if      (k < 256)  v = W1[(size_t)k * HID + n];
        else if (k < 384)  v = W1[(size_t)(k + 32) * HID + n];
        else if (k < 416)  v = W1[(size_t)(k - 128) * HID + n];
        else if (k < 432)  v = W1[(size_t)k * HID + n];
        else if (k == 432) v = b1[n];
        else               v = 0.f;
        off = (uint32_t)(k >> 6) * 32768u + amap(n, k & 63);
    } else if (idx < 73728) {                // L2
        int i2 = idx - 57344, k = i2 >> 7, n = i2 & 127;
        v = W2[(size_t)k * HID + n];
        off = IMG_B2 + (uint32_t)(k >> 6) * 32768u + amap(n, k & 63);
    } else if (idx < 122880) {               // L3 tile t
        int i3 = idx - 73728, t = i3 >> 14, rem = i3 & 16383, k = rem >> 7, n = rem & 127;
        v = W3[(size_t)k * 384 + 128 * t + n];
        off = IMG_B3 + (uint32_t)(t * 2 + (k >> 6)) * 32768u + amap(n, k & 63);
    } else if (idx < 172032) {               // Wvp tile t
        int i4 = idx - 122880, t = i4 >> 14, rem = i4 & 16383, k = rem >> 7, n = rem & 127;
        v = Wvp[(size_t)k * 384 + 128 * t + n];
        off = IMG_BVP + (uint32_t)(t * 2 + (k >> 6)) * 32768u + amap(n, k & 63);
    } else {                                 // Wop tile t
        int i5 = idx - 172032, t = i5 >> 14, rem = i5 & 16383, k = rem >> 7, n = rem & 127;
        v = Wop[(size_t)k * 384 + 128 * t + n];
        off = IMG_BOP + (uint32_t)(t * 2 + (k >> 6)) * 32768u + amap(n, k & 63);
    }
    unsigned short hi, lo; hilo(v, hi, lo);
    *(unsigned short*)(g_wimg + off)         = hi;
    *(unsigned short*)(g_wimg + off + 16384) = lo;
}

// ======================= zero =======================
__global__ void k_zero() {
    int i = blockIdx.x * blockDim.x + threadIdx.x;
    const int n1 = NN * HID / 4;
    float4 z = make_float4(0.f, 0.f, 0.f, 0.f);
    if (i < n1) reinterpret_cast<float4*>(g_haggr)[i] = z;
    else        reinterpret_cast<float4*>(g_vaggr)[i - n1] = z;
}

// ======================= generic 64-row GEMM: src[M,128] @ W[128,384] =======================
#define GM_A 0u          // hi q*8192 ; lo 16384 + q*8192
#define GM_B 32768u      // 2 x 32KB ping-pong
#define GM_TOT 98304

__global__ void __launch_bounds__(256, 2) k_gemm(const float* __restrict__ srcp,
                                                 int Mtot, uint32_t wbase, int mode) {
    extern __shared__ __align__(1024) unsigned char sm[];
    const int tid = threadIdx.x, w = tid >> 5, l = tid & 31;
    const int r0 = blockIdx.x * 64;
    const uint32_t sb = smem_u32(sm);
    const float* src = (mode == 0) ? srcp : g_haggr;

#define GCOPYB(goff, s) do { \
    const unsigned char* _s = g_wimg + (goff); \
    uint32_t _d = sb + GM_B + (uint32_t)(s) * 32768u; \
    for (int _i = tid; _i < 2048; _i += 256) \
        CPA16(_d + ((uint32_t)_i << 4), _s + ((size_t)_i << 4)); \
    CPA_COMMIT(); } while (0)

    GCOPYB(wbase, 0);

    // build A: 64 rows x 128 K, hi/lo, coalesced
    {
        const int eb = (w << 1) + (l >> 4);
        const int hl = l & 15;
#pragma unroll 1
        for (int pass = 0; pass < 4; pass++) {
            int e = pass * 16 + eb;
            int rg = r0 + e;
            bool valid = rg < Mtot;
#pragma unroll
            for (int qp = 0; qp < 2; qp++) {
                float4 v4 = make_float4(0.f, 0.f, 0.f, 0.f);
                if (valid) v4 = *(const float4*)&src[(size_t)rg * 128 + qp * 64 + 4 * hl];
                unsigned short h0, l0, h1, l1, h2, l2, h3, l3;
                hilo(v4.x, h0, l0); hilo(v4.y, h1, l1);
                hilo(v4.z, h2, l2); hilo(v4.w, h3, l3);
                uint32_t off = (uint32_t)qp * 8192u + amap(e, 4 * hl);
                *(uint2*)(sm + GM_A + off) =
                    make_uint2((uint32_t)h0 | ((uint32_t)h1 << 16), (uint32_t)h2 | ((uint32_t)h3 << 16));
                *(uint2*)(sm + GM_A + 16384u + off) =
                    make_uint2((uint32_t)l0 | ((uint32_t)l1 << 16), (uint32_t)l2 | ((uint32_t)l3 << 16));
            }
        }
    }

    const int wm = w & 3, nh = w >> 2;
    const int gr = (wm << 4) + (l >> 2);
    const uint32_t a_lane = (((uint32_t)(2 * wm + ((l >> 3) & 1))) << 10) | (((uint32_t)(l & 7)) << 7);
    const uint32_t lmask  = ((uint32_t)(l & 7)) << 4;
    const int ak_extra = (l >> 4) << 3;
    const uint32_t b_lane = (((uint32_t)((l >> 4) & 1)) << 10) | (((uint32_t)(l & 7)) << 7);
    const uint32_t nh_off = (uint32_t)nh * 8192u;
    const int bk_extra = (l & 8);
    const int cq = 2 * (l & 3);

#define GRUN4(ACC, APAN, BUF) do { \
    uint32_t _bb = sb + GM_B + (uint32_t)(BUF) * 32768u; \
    _Pragma("unroll") \
    for (int s = 0; s < 4; s++) { \
        int kb = s << 4; \
        uint32_t aHi = sb + (APAN) + a_lane + ((((uint32_t)(kb + ak_extra)) << 1) ^ lmask); \
        uint32_t bHi = _bb + b_lane + nh_off + ((((uint32_t)(kb + bk_extra)) << 1) ^ lmask); \
        uint32_t ah[4], al[4]; \
        ldsm4(ah, aHi); ldsm4(al, aHi + 16384u); \
        _Pragma("unroll") \
        for (int np = 0; np < 4; np++) { \
            uint32_t bh[4], bl[4]; \
            ldsm4(bh, bHi + ((uint32_t)np << 11)); \
            ldsm4(bl, bHi + 16384u + ((uint32_t)np << 11)); \
            mma16816((ACC)[2 * np],     ah, bh[0], bh[1]); \
            mma16816((ACC)[2 * np],     al, bh[0], bh[1]); \
            mma16816((ACC)[2 * np],     ah, bl[0], bl[1]); \
            mma16816((ACC)[2 * np + 1], ah, bh[2], bh[3]); \
            mma16816((ACC)[2 * np + 1], al, bh[2], bh[3]); \
            mma16816((ACC)[2 * np + 1], ah, bl[2], bl[3]); \
        } \
    } } while (0)

    float acc[8][4];
    for (int t = 0; t < 3; t++) {
#pragma unroll
        for (int nt = 0; nt < 8; nt++)
#pragma unroll
            for (int q = 0; q < 4; q++) acc[nt][q] = 0.f;
        for (int q = 0; q < 2; q++) {
            int i = t * 2 + q;
            if (i < 5) { GCOPYB(wbase + (uint32_t)(i + 1) * 32768u, (i + 1) & 1); CPA_WAIT1(); }
            else CPA_WAIT0();
            __syncthreads();
            GRUN4(acc, GM_A + (uint32_t)q * 8192u, i & 1);
            __syncthreads();
        }
#pragma unroll
        for (int nt = 0; nt < 8; nt++) {
            int col = 64 * nh + 8 * nt + cq;
#pragma unroll
            for (int hf = 0; hf < 2; hf++) {
                int rg = r0 + gr + 8 * hf;
                if (rg < Mtot) {
                    float* p;
                    if (mode == 0) p = ((t == 0) ? g_v1 : (t == 1) ? g_v2 : g_v3) + (size_t)rg * 128 + col;
                    else           p = g_o + (size_t)rg * 384 + 128 * t + col;
                    *(float2*)p = make_float2(acc[nt][2 * hf], acc[nt][2 * hf + 1]);
                }
            }
        }
    }
#undef GRUN4
#undef GCOPYB
}

// ======================= final elementwise: dh, dvec (+vdot) =======================
__global__ __launch_bounds__(256) void k_final(const float* __restrict__ bop,
                                               float* __restrict__ out) {
    int g = blockIdx.x * 256 + threadIdx.x;
    int n = g >> 5, c = (g & 31) * 4;
    const float* op = g_o + (size_t)n * 384;
    float4 o1 = *(const float4*)&op[c];
    float4 o2 = *(const float4*)&op[128 + c];
    float4 o3 = *(const float4*)&op[256 + c];
    float4 b1v = *(const float4*)&bop[c];
    float4 b2v = *(const float4*)&bop[128 + c];
    float4 b3v = *(const float4*)&bop[256 + c];
    o1.x += b1v.x; o1.y += b1v.y; o1.z += b1v.z; o1.w += b1v.w;
    o2.x += b2v.x; o2.y += b2v.y; o2.z += b2v.z; o2.w += b2v.w;
    o3.x += b3v.x; o3.y += b3v.y; o3.z += b3v.z; o3.w += b3v.w;
    float vd[4] = {0.f, 0.f, 0.f, 0.f};
#pragma unroll
    for (int v = 0; v < 3; v++) {
        size_t base = ((size_t)n * 3 + v) * 128 + c;
        float4 a = *(const float4*)&g_v1[base];
        float4 b = *(const float4*)&g_v2[base];
        vd[0] += a.x * b.x; vd[1] += a.y * b.y; vd[2] += a.z * b.z; vd[3] += a.w * b.w;
    }
    *(float4*)&out[(size_t)n * 128 + c] =
        make_float4(vd[0] * o2.x + o3.x, vd[1] * o2.y + o3.y,
                    vd[2] * o2.z + o3.z, vd[3] * o2.w + o3.w);
#pragma unroll
    for (int v = 0; v < 3; v++) {
        size_t base = ((size_t)n * 3 + v) * 128 + c;
        float4 v3 = *(const float4*)&g_v3[base];
        float4 va = *(const float4*)&g_vaggr[base];
        *(float4*)&out[(size_t)NN * 128 + base] =
            make_float4(v3.x * o1.x + va.x, v3.y * o1.y + va.y,
                        v3.z * o1.z + va.z, v3.w * o1.w + va.w);
    }
}

// ======================= tensorized edge kernel (64 edges/CTA, 2 CTA/SM, batched phases) =======================
// SMEM: C/A union 32KB @0:
//   L1 A-build: slot qp (0/1): hi @ qp*16384, lo @ qp*16384+8192
//   activations C: hi panel q @ q*8192, lo @ 16384 + q*8192
// B: 64KB @32768 (2 panel-pairs, panel q at 32768 + q*32768)
// meta @98304
#define SMM_C 0u
#define SMM_B 32768u
#define SMM_META 98304u
#define SMM_TOT  102400

__global__ void __launch_bounds__(256, 2) k_edge_m(const float* __restrict__ h,
                                                   const float* __restrict__ coord,
                                                   const int*   __restrict__ ei,
                                                   const float* __restrict__ eattr,
                                                   const float* __restrict__ b2g,
                                                   const float* __restrict__ b3g) {
    extern __shared__ __align__(1024) unsigned char sm[];
    const int tid = threadIdx.x, w = tid >> 5, l = tid & 31;
    const int e0 = blockIdx.x * 64;
    const uint32_t sb = smem_u32(sm);
    int*   row_sh = (int*)  (sm + SMM_META);
    int*   col_sh = (int*)  (sm + SMM_META + 256);
    float* xij    = (float*)(sm + SMM_META + 512);
    float* dsh    = (float*)(sm + SMM_META + 1280);
    float* sb2    = (float*)(sm + SMM_META + 1536);
    float* sb3    = (float*)(sm + SMM_META + 2048);

    if (tid < 128) sb2[tid] = b2g[tid];
    if (tid < 192) { sb3[tid * 2] = b3g[tid * 2]; sb3[tid * 2 + 1] = b3g[tid * 2 + 1]; }
    if (tid < 64) {
        int e = e0 + tid;
        int r = ei[e], c = ei[EE + e];
        row_sh[tid] = r; col_sh[tid] = c;
        float dx = coord[3 * r] - coord[3 * c];
        float dy = coord[3 * r + 1] - coord[3 * c + 1];
        float dz = coord[3 * r + 2] - coord[3 * c + 2];
        xij[3 * tid] = dx; xij[3 * tid + 1] = dy; xij[3 * tid + 2] = dz;
        dsh[tid] = sqrtf(dx * dx + dy * dy + dz * dz + 1e-8f);
    }
    __syncthreads();

    const int wm = w & 3, nh = w >> 2;
    const int gr = (wm << 4) + (l >> 2);
    const uint32_t a_lane = (((uint32_t)(2 * wm + ((l >> 3) & 1))) << 10) | (((uint32_t)(l & 7)) << 7);
    const uint32_t lmask  = ((uint32_t)(l & 7)) << 4;
    const int ak_extra = (l >> 4) << 3;
    const uint32_t b_lane = (((uint32_t)((l >> 4) & 1)) << 10) | (((uint32_t)(l & 7)) << 7);
    const uint32_t nh_off = (uint32_t)nh * 8192u;
    const int bk_extra = (l & 8);
    const int cq = 2 * (l & 3);

    float acc[8][4];
#pragma unroll
    for (int t = 0; t < 8; t++)
#pragma unroll
        for (int q = 0; q < 4; q++) acc[t][q] = 0.f;

#define RUN4(ACC, APAN, ALOFF, BBASE) do { \
    uint32_t _bb = sb + (BBASE); \
    _Pragma("unroll") \
    for (int s = 0; s < 4; s++) { \
        int kb = s << 4; \
        uint32_t aHi = sb + (APAN) + a_lane + ((((uint32_t)(kb + ak_extra)) << 1) ^ lmask); \
        uint32_t bHi = _bb + b_lane + nh_off + ((((uint32_t)(kb + bk_extra)) << 1) ^ lmask); \
        uint32_t ah[4], al[4]; \
        ldsm4(ah, aHi); ldsm4(al, aHi + (ALOFF)); \
        _Pragma("unroll") \
        for (int np = 0; np < 4; np++) { \
            uint32_t bh[4], bl[4]; \
            ldsm4(bh, bHi + ((uint32_t)np << 11)); \
            ldsm4(bl, bHi + 16384u + ((uint32_t)np << 11)); \
            mma16816((ACC)[2 * np],     ah, bh[0], bh[1]); \
            mma16816((ACC)[2 * np],     al, bh[0], bh[1]); \
            mma16816((ACC)[2 * np],     ah, bl[0], bl[1]); \
            mma16816((ACC)[2 * np + 1], ah, bh[2], bh[3]); \
            mma16816((ACC)[2 * np + 1], al, bh[2], bh[3]); \
            mma16816((ACC)[2 * np + 1], ah, bl[2], bl[3]); \
        } \
    } } while (0)

#define COPYB(goff, n16) do { \
    const unsigned char* _s = g_wimg + (goff); \
    for (int _i = tid; _i < (n16); _i += 256) \
        CPA16(sb + SMM_B + ((uint32_t)_i << 4), _s + ((size_t)_i << 4)); \
    CPA_COMMIT(); } while (0)

    // ---------------- Layer 1: 4 batched phases (2 panels each; last has 1) ----------------
    {
        const int eb = (w << 1) + (l >> 4);     // edge within 16-edge pass group
        const int hl = l & 15;                  // 16B chunk: cols 4hl..4hl+3
        for (int b = 0; b < 4; b++) {
            int p0 = 2 * b, npan = (b < 3) ? 2 : 1;
            COPYB((size_t)p0 * 32768u, npan * 2048);
#pragma unroll 1
            for (int qp = 0; qp < 2; qp++) {
                if (qp >= npan) break;
                int p = p0 + qp;
                uint32_t abase = (uint32_t)qp * 16384u;
#pragma unroll 1
                for (int pass = 0; pass < 4; pass++) {
                    int e = pass * 16 + eb;
                    float4 v4;
                    if (p < 4) {
                        int node = (p < 2) ? row_sh[e] : col_sh[e];
                        v4 = *(const float4*)&h[(size_t)node * HID + 64 * (p & 1) + 4 * hl];
                    } else if (p < 6) {
                        int rr = row_sh[e], cc = col_sh[e];
                        int base = 64 * (p - 4) + 4 * hl;
                        v4 = make_float4(0.f, 0.f, 0.f, 0.f);
#pragma unroll
                        for (int vv = 0; vv < 3; vv++) {
                            float4 a4 = *(const float4*)&g_v1[((size_t)rr * 3 + vv) * HID + base];
                            float4 c4 = *(const float4*)&g_v2[((size_t)cc * 3 + vv) * HID + base];
                            v4.x += a4.x * c4.x; v4.y += a4.y * c4.y;
                            v4.z += a4.z * c4.z; v4.w += a4.w * c4.w;
                        }
                    } else {
                        float dd = dsh[e];
                        float vv[4];
#pragma unroll
                        for (int q = 0; q < 4; q++) {
                            int kk = 4 * hl + q;
                            if (kk < 32) { float t0 = dd - (5.f / 31.f) * kk; vv[q] = __expf(RBF_COEFF * t0 * t0); }
                            else vv[q] = (kk == 48) ? 1.f : 0.f;
                        }
                        if (hl >= 8 && hl < 12) {
                            float4 ea = *(const float4*)&eattr[(size_t)(e0 + e) * 16 + (4 * hl - 32)];
                            vv[0] = ea.x; vv[1] = ea.y; vv[2] = ea.z; vv[3] = ea.w;
                        }
                        v4 = make_float4(vv[0], vv[1], vv[2], vv[3]);
                    }
                    unsigned short h0, l0, h1, l1, h2, l2, h3, l3;
                    hilo(v4.x, h0, l0); hilo(v4.y, h1, l1);
                    hilo(v4.z, h2, l2); hilo(v4.w, h3, l3);
                    uint32_t off = abase + amap(e, 4 * hl);
                    *(uint2*)(sm + SMM_C + off) =
                        make_uint2((uint32_t)h0 | ((uint32_t)h1 << 16), (uint32_t)h2 | ((uint32_t)h3 << 16));
                    *(uint2*)(sm + SMM_C + 8192u + off) =
                        make_uint2((uint32_t)l0 | ((uint32_t)l1 << 16), (uint32_t)l2 | ((uint32_t)l3 << 16));
                }
            }
            CPA_WAIT0();
            __syncthreads();
            RUN4(acc, SMM_C + 0u, 8192u, SMM_B);
            if (npan == 2) RUN4(acc, SMM_C + 16384u, 8192u, SMM_B + 32768u);
            __syncthreads();
        }
    }
    // L2 weights copy (64KB) overlaps epilogue 1
    COPYB(IMG_B2, 4096);
    // epilogue 1: silu (bias folded), write activations C
#pragma unroll
    for (int nt = 0; nt < 8; nt++) {
        int col = 64 * nh + 8 * nt + cq;
        uint32_t pan = (col >= 64) ? 8192u : 0u;
        uint32_t ko = (uint32_t)(col & 63);
#pragma unroll
        for (int hf = 0; hf < 2; hf++) {
            int row = gr + 8 * hf;
            float z0 = acc[nt][2 * hf], z1 = acc[nt][2 * hf + 1];
            z0 = z0 / (1.f + __expf(-z0));
            z1 = z1 / (1.f + __expf(-z1));
            unsigned short h0, l0, h1, l1;
            hilo(z0, h0, l0); hilo(z1, h1, l1);
            uint32_t off = pan + amap(row, ko);
            *(uint32_t*)(sm + SMM_C + off)          = (uint32_t)h0 | ((uint32_t)h1 << 16);
            *(uint32_t*)(sm + SMM_C + 16384u + off) = (uint32_t)l0 | ((uint32_t)l1 << 16);
        }
    }
#pragma unroll
    for (int t = 0; t < 8; t++)
#pragma unroll
        for (int q = 0; q < 4; q++) acc[t][q] = 0.f;
    CPA_WAIT0();
    __syncthreads();

    // ---------------- Layer 2: single phase ----------------
    RUN4(acc, SMM_C + 0u,    16384u, SMM_B);
    RUN4(acc, SMM_C + 8192u, 16384u, SMM_B + 32768u);
    __syncthreads();
    // t=2 weights copy overlaps epilogue 2
    COPYB(IMG_B3 + 4u * 32768u, 4096);
    // epilogue 2: +b2, silu, overwrite C with A3
#pragma unroll
    for (int nt = 0; nt < 8; nt++) {
        int col = 64 * nh + 8 * nt + cq;
        uint32_t pan = (col >= 64) ? 8192u : 0u;
        uint32_t ko = (uint32_t)(col & 63);
        float bb0 = sb2[col], bb1 = sb2[col + 1];
#pragma unroll
        for (int hf = 0; hf < 2; hf++) {
            int row = gr + 8 * hf;
            float z0 = acc[nt][2 * hf] + bb0, z1 = acc[nt][2 * hf + 1] + bb1;
            z0 = z0 / (1.f + __expf(-z0));
            z1 = z1 / (1.f + __expf(-z1));
            unsigned short h0, l0, h1, l1;
            hilo(z0, h0, l0); hilo(z1, h1, l1);
            uint32_t off = pan + amap(row, ko);
            *(uint32_t*)(sm + SMM_C + off)          = (uint32_t)h0 | ((uint32_t)h1 << 16);
            *(uint32_t*)(sm + SMM_C + 16384u + off) = (uint32_t)l0 | ((uint32_t)l1 << 16);
        }
    }
    __syncthreads();

    // ---------------- Layer 3 ----------------
    {
        float acx[8][4];
        // t=2 (msg_x) -> acx
#pragma unroll
        for (int t = 0; t < 8; t++)
#pragma unroll
            for (int q = 0; q < 4; q++) acx[t][q] = 0.f;
        CPA_WAIT0();
        __syncthreads();
        RUN4(acx, SMM_C + 0u,    16384u, SMM_B);
        RUN4(acx, SMM_C + 8192u, 16384u, SMM_B + 32768u);
        __syncthreads();
        // t=1 (msg_v) -> acc
        COPYB(IMG_B3 + 2u * 32768u, 4096);
#pragma unroll
        for (int t = 0; t < 8; t++)
#pragma unroll
            for (int q = 0; q < 4; q++) acc[t][q] = 0.f;
        // add msg_x bias while copy is in flight
#pragma unroll
        for (int nt = 0; nt < 8; nt++) {
            int col = 64 * nh + 8 * nt + cq;
#pragma unroll
            for (int hf = 0; hf < 2; hf++) {
                acx[nt][2 * hf]     += sb3[256 + col];
                acx[nt][2 * hf + 1] += sb3[256 + col + 1];
            }
        }
        CPA_WAIT0();
        __syncthreads();
        RUN4(acc, SMM_C + 0u,    16384u, SMM_B);
        RUN4(acc, SMM_C + 8192u, 16384u, SMM_B + 32768u);
        __syncthreads();
        // t=0 weights copy overlaps vaggr scatter
        COPYB(IMG_B3, 4096);
#pragma unroll
        for (int nt = 0; nt < 8; nt++) {
            int col = 64 * nh + 8 * nt + cq;
#pragma unroll
            for (int hf = 0; hf < 2; hf++) {
                acc[nt][2 * hf]     += sb3[128 + col];
                acc[nt][2 * hf + 1] += sb3[128 + col + 1];
            }
        }
#pragma unroll 1
        for (int hf = 0; hf < 2; hf++) {
            int er = gr + 8 * hf;
            int ro = row_sh[er], co = col_sh[er];
            float x0 = xij[3 * er], x1 = xij[3 * er + 1], x2 = xij[3 * er + 2];
#pragma unroll 1
            for (int v = 0; v < 3; v++) {
                float xv = (v == 0) ? x0 : (v == 1) ? x1 : x2;
                const float* vbp = &g_v3[((size_t)co * 3 + v) * HID];
                float* abp = &g_vaggr[((size_t)ro * 3 + v) * HID];
#pragma unroll
                for (int nt = 0; nt < 8; nt++) {
                    int c0 = 64 * nh + 8 * nt + cq;
                    float2 v3v = *(const float2*)(vbp + c0);
                    RED2(abp + c0,
                         v3v.x * acc[nt][2 * hf]     + acx[nt][2 * hf]     * xv,
                         v3v.y * acc[nt][2 * hf + 1] + acx[nt][2 * hf + 1] * xv);
                }
            }
        }
        // t=0 (msg_h) -> acx (reuse), scatter haggr
#pragma unroll
        for (int t = 0; t < 8; t++)
#pragma unroll
            for (int q = 0; q < 4; q++) acx[t][q] = 0.f;
        CPA_WAIT0();
        __syncthreads();
        RUN4(acx, SMM_C + 0u,    16384u, SMM_B);
        RUN4(acx, SMM_C + 8192u, 16384u, SMM_B + 32768u);
#pragma unroll 1
        for (int hf = 0; hf < 2; hf++) {
            int er = gr + 8 * hf;
            int ro = row_sh[er];
            float* hbp = &g_haggr[(size_t)ro * HID];
#pragma unroll
            for (int nt = 0; nt < 8; nt++) {
                int c0 = 64 * nh + 8 * nt + cq;
                RED2(hbp + c0,
                     acx[nt][2 * hf]     + sb3[c0],
                     acx[nt][2 * hf + 1] + sb3[c0 + 1]);
            }
        }
    }
#undef RUN4
#undef COPYB
}

// ======================= launch =======================
extern "C" void kernel_launch(void* const* d_in, const int* in_sizes, int n_in,
                              void* d_out, int out_size) {
    const float* h     = (const float*)d_in[0];
    const float* vec   = (const float*)d_in[1];
    const float* coord = (const float*)d_in[2];
    const int*   ei    = (const int*)  d_in[3];
    const float* eattr = (const float*)d_in[4];
    const float* Wvp   = (const float*)d_in[5];
    const float* W1    = (const float*)d_in[6];
    const float* b1    = (const float*)d_in[7];
    const float* W2    = (const float*)d_in[8];
    const float* b2    = (const float*)d_in[9];
    const float* W3    = (const float*)d_in[10];
    const float* b3    = (const float*)d_in[11];
    const float* Wop   = (const float*)d_in[12];
    const float* bop   = (const float*)d_in[13];
    float* out = (float*)d_out;

    cudaFuncSetAttribute(k_edge_m, cudaFuncAttributeMaxDynamicSharedMemorySize, SMM_TOT);
    cudaFuncSetAttribute(k_gemm,   cudaFuncAttributeMaxDynamicSharedMemorySize, GM_TOT);

    k_prep<<<864, 256>>>(W1, b1, W2, W3, Wvp, Wop);
    k_zero<<<25000, 256>>>();
    k_gemm<<<2344, 256, GM_TOT>>>(vec, 3 * NN, IMG_BVP, 0);           // vecp -> v1/v2/v3
    k_edge_m<<<EE / 64, 256, SMM_TOT>>>(h, coord, ei, eattr, b2, b3);
    k_gemm<<<782, 256, GM_TOT>>>(nullptr, NN, IMG_BOP, 1);            // h_aggr @ Wop -> g_o
    k_final<<<NN * 32 / 256, 256>>>(bop, out);
}